// round 10
// baseline (speedup 1.0000x reference)
#include <cuda_runtime.h>
#include <cuda_fp16.h>
#include <mma.h>
#include <math.h>
#include <stdint.h>

using namespace nvcuda;

// Problem dims
#define Bq   2
#define Sq   2048
#define Eq   1024
#define Hq   16
#define DKq  64
#define Mq   (Bq*Sq)    // 4096
#define BHq  (Bq*Hq)    // 32
#define LN_EPS 1e-5f
#define LOG2E 1.442695040888963f

typedef __half f16;

// ---------------- scratch (device globals; no allocs allowed) ----------------
__device__ f16   g_xh[Mq*Eq];
__device__ f16   g_wqh[Eq*Eq];
__device__ f16   g_wkh[Eq*Eq];
__device__ f16   g_wvh[Eq*Eq];
__device__ f16   g_woh[Eq*Eq];
__device__ f16   g_qh[Mq*Eq];           // q f16, pre-scaled by 0.125*log2e
__device__ f16   g_kh[Mq*Eq];
__device__ f16   g_vh[Mq*Eq];
__device__ f16   g_mixed[Mq*Eq];        // attention result (+c_attn), f16
__device__ float g_attnout[Mq*Eq];      // mixed @ wo, fp32
__device__ float g_ffnvec[Eq];          // data-free FFN output vector
__device__ float g_cattn;

__device__ __forceinline__ void cpa16(uint32_t dst, const void* src) {
    asm volatile("cp.async.cg.shared.global [%0], [%1], 16;\n" :: "r"(dst), "l"(src));
}

// ---------------- prep: quantum scalars + collapsed FFN vector ----------------
__global__ void prep_kernel(const float* __restrict__ qp_attn,
                            const float* __restrict__ qp_ffn,
                            const float* __restrict__ w2,
                            const float* __restrict__ b2) {
    int e = threadIdx.x;
    if (e == 0) g_cattn = cosf(qp_attn[0] + qp_attn[1]);
    float cf = cosf(qp_ffn[0] + qp_ffn[1]);
    float rf = cf > 0.f ? cf : 0.f;   // relu
    if (e < Eq) {
        g_ffnvec[e] = rf * (w2[e] + w2[Eq + e] + w2[2*Eq + e] + w2[3*Eq + e]) + b2[e];
    }
}

// ---------------- fp32 -> f16 conversion ------------------------
__global__ __launch_bounds__(256)
void conv_x_kernel(const float* __restrict__ s, f16* __restrict__ d, int n4) {
    int i = blockIdx.x * blockDim.x + threadIdx.x;
    if (i < n4) {
        float4 v = ((const float4*)s)[i];
        ((__half2*)d)[2*i]   = __floats2half2_rn(v.x, v.y);
        ((__half2*)d)[2*i+1] = __floats2half2_rn(v.z, v.w);
    }
}
__global__ __launch_bounds__(256)
void conv_w_kernel(const float* __restrict__ wq, const float* __restrict__ wk,
                   const float* __restrict__ wv, const float* __restrict__ wo) {
    int i = blockIdx.x * blockDim.x + threadIdx.x;
    const int n4 = Eq*Eq/4;
    if (i >= n4) return;
    const float* s; f16* d;
    switch (blockIdx.y) {
        case 0:  s = wq; d = g_wqh; break;
        case 1:  s = wk; d = g_wkh; break;
        case 2:  s = wv; d = g_wvh; break;
        default: s = wo; d = g_woh; break;
    }
    float4 v = ((const float4*)s)[i];
    ((__half2*)d)[2*i]   = __floats2half2_rn(v.x, v.y);
    ((__half2*)d)[2*i+1] = __floats2half2_rn(v.z, v.w);
}

// ---------------- f16 WMMA GEMM core (cp.async 2-stage, BK=64) -----------------
// Block 128x128, BK=64, 128 threads = 4 warps (2m x 2n), warp tile 64x64.
// Dynamic smem: A stages [0, 2*18432), B stages [36864, 36864+2*17408)
#define AS_LD 72
#define BS_LD 136
#define A_STG (128*AS_LD)          // halves per A stage (9216)
#define B_STG (64*BS_LD)           // halves per B stage (8704)
#define G_OFF_B (2*A_STG*2)        // 36864 bytes
#define G_SMEM  (G_OFF_B + 2*B_STG*2)   // 71680 bytes
#define STG_LD 20                  // epilogue staging stride (floats), mult of 4

struct GemmCore {
    wmma::fragment<wmma::accumulator, 16, 16, 16, float> acc[4][4];

    __device__ __forceinline__ void run(const f16* A, const f16* B,
                                        int m0, int n0, char* dynsm, int tid) {
        const int wid = tid >> 5;
        const int wm  = wid & 1, wn = wid >> 1;
        f16* As = (f16*)dynsm;
        f16* Bs = (f16*)(dynsm + G_OFF_B);
        const uint32_t asb = (uint32_t)__cvta_generic_to_shared(As);
        const uint32_t bsb = (uint32_t)__cvta_generic_to_shared(Bs);

        // A tile 128x64: rows r0+16i, cols (tid&7)*8 ; 8 chunks/thread
        // B tile 64x128: rows rb+8i,  cols (tid&15)*8; 8 chunks/thread
        const int r0 = tid >> 3,  c8  = (tid & 7) * 8;
        const int rb = tid >> 4,  cb8 = (tid & 15) * 8;
        const f16* aB = A + (size_t)(m0 + r0) * Eq + c8;
        const f16* bB = B + (size_t)rb * Eq + n0 + cb8;
        uint32_t aD[8], bD[8];
        #pragma unroll
        for (int i = 0; i < 8; i++) {
            aD[i] = asb + (uint32_t)((r0 + 16*i)*AS_LD + c8) * 2;
            bD[i] = bsb + (uint32_t)((rb + 8*i)*BS_LD + cb8) * 2;
        }
        #pragma unroll
        for (int mi = 0; mi < 4; mi++)
            #pragma unroll
            for (int ni = 0; ni < 4; ni++)
                wmma::fill_fragment(acc[mi][ni], 0.0f);

        const int niter = Eq / 64;   // 16
        #pragma unroll
        for (int i = 0; i < 8; i++) cpa16(aD[i], aB + (size_t)(16*i)*Eq);
        #pragma unroll
        for (int i = 0; i < 8; i++) cpa16(bD[i], bB + (size_t)(8*i)*Eq);
        asm volatile("cp.async.commit_group;\n");

        for (int kb = 0; kb < niter; kb++) {
            const int cur = kb & 1;
            if (kb + 1 < niter) {
                const int nxt = (kb + 1) & 1;
                const uint32_t ao = (uint32_t)(nxt * A_STG) * 2;
                const uint32_t bo = (uint32_t)(nxt * B_STG) * 2;
                const int koffA = (kb + 1) * 64;
                const size_t koffB = (size_t)(kb + 1) * 64 * Eq;
                #pragma unroll
                for (int i = 0; i < 8; i++)
                    cpa16(aD[i] + ao, aB + (size_t)(16*i)*Eq + koffA);
                #pragma unroll
                for (int i = 0; i < 8; i++)
                    cpa16(bD[i] + bo, bB + (size_t)(8*i)*Eq + koffB);
                asm volatile("cp.async.commit_group;\n");
                asm volatile("cp.async.wait_group 1;\n");
            } else {
                asm volatile("cp.async.wait_group 0;\n");
            }
            __syncthreads();
            const f16* Ac = As + cur * A_STG;
            const f16* Bc = Bs + cur * B_STG;
            #pragma unroll
            for (int ks = 0; ks < 4; ks++) {
                wmma::fragment<wmma::matrix_a, 16, 16, 16, f16, wmma::row_major> af[4];
                wmma::fragment<wmma::matrix_b, 16, 16, 16, f16, wmma::row_major> bfr[4];
                #pragma unroll
                for (int mi = 0; mi < 4; mi++)
                    wmma::load_matrix_sync(af[mi], Ac + (wm*64 + mi*16)*AS_LD + ks*16, AS_LD);
                #pragma unroll
                for (int ni = 0; ni < 4; ni++)
                    wmma::load_matrix_sync(bfr[ni], Bc + (ks*16)*BS_LD + wn*64 + ni*16, BS_LD);
                #pragma unroll
                for (int mi = 0; mi < 4; mi++)
                    #pragma unroll
                    for (int ni = 0; ni < 4; ni++)
                        wmma::mma_sync(acc[mi][ni], af[mi], bfr[ni], acc[mi][ni]);
            }
            __syncthreads();
        }
    }
};

// fused QKV projection: grid (24, 32); blockIdx.x selects tensor + n-block
__global__ __launch_bounds__(128, 2)
void gemm_qkv(float qscale) {
    extern __shared__ char dynsm[];
    const int tid = threadIdx.x;
    const int wid = tid >> 5, lane = tid & 31;
    const int wm  = wid & 1, wn = wid >> 1;
    const int t   = blockIdx.x >> 3;           // 0=q, 1=k, 2=v
    const int n0  = (blockIdx.x & 7) * 128;
    const int m0  = blockIdx.y * 128;
    const f16* B = (t == 0) ? g_wqh : (t == 1) ? g_wkh : g_wvh;
    f16*       C = (t == 0) ? g_qh  : (t == 1) ? g_kh  : g_vh;
    const float scale = (t == 0) ? qscale : 1.0f;

    GemmCore core;
    core.run(g_xh, B, m0, n0, dynsm, tid);

    float* stgw = ((float*)dynsm) + wid * (16*STG_LD);
    const int srow = lane >> 1, scol = (lane & 1) * 8;
    #pragma unroll
    for (int mi = 0; mi < 4; mi++) {
        #pragma unroll
        for (int ni = 0; ni < 4; ni++) {
            #pragma unroll
            for (int tt = 0; tt < core.acc[mi][ni].num_elements; tt++)
                core.acc[mi][ni].x[tt] *= scale;
            wmma::store_matrix_sync(stgw, core.acc[mi][ni], STG_LD, wmma::mem_row_major);
            __syncwarp();
            const float* sp = stgw + srow*STG_LD + scol;
            union { f16 h[8]; uint4 u; } tmp;
            #pragma unroll
            for (int j = 0; j < 8; j += 2) {
                __half2 p = __floats2half2_rn(sp[j], sp[j+1]);
                tmp.h[j] = p.x;  tmp.h[j+1] = p.y;
            }
            f16* cp = C + (size_t)(m0 + wm*64 + mi*16 + srow) * Eq
                        + n0 + wn*64 + ni*16 + scol;
            *(uint4*)cp = tmp.u;
            __syncwarp();
        }
    }
}

// wo projection: fp32 out
__global__ __launch_bounds__(128, 2)
void gemm_wo() {
    extern __shared__ char dynsm[];
    const int tid = threadIdx.x;
    const int wid = tid >> 5;
    const int wm  = wid & 1, wn = wid >> 1;
    const int m0  = blockIdx.y * 128, n0 = blockIdx.x * 128;

    GemmCore core;
    core.run(g_mixed, g_woh, m0, n0, dynsm, tid);

    #pragma unroll
    for (int mi = 0; mi < 4; mi++)
        #pragma unroll
        for (int ni = 0; ni < 4; ni++)
            wmma::store_matrix_sync(g_attnout + (size_t)(m0 + wm*64 + mi*16) * Eq
                                    + n0 + wn*64 + ni*16,
                                    core.acc[mi][ni], Eq, wmma::mem_row_major);
}

// ---------------- fused flash attention (f16, Q-tile 128, key-tile 64) --------
// 256 threads (8 warps). Q frags in registers. Half-accum QK^T -> h2exp2 on
// packed half2 fragment -> P f16 (warp-private). Row sums via ones-column in V.
#define QS_LD 72
#define KS_LD 72
#define VS_LD 88
#define PS_LD 72
#define OST_LD 84
#define OFF_QS 0
#define OFF_KS (128*QS_LD*2)
#define OFF_VS (OFF_KS + 2*64*KS_LD*2)
#define OFF_PS (OFF_VS + 2*64*VS_LD*2)
#define SMEM_FLASH (OFF_PS + 128*PS_LD*2)

__global__ __launch_bounds__(256)
void flash_f16() {
    extern __shared__ char dynsm[];
    f16*   Qs  = (f16*)(dynsm + OFF_QS);
    f16*   Ks  = (f16*)(dynsm + OFF_KS);
    f16*   Vs  = (f16*)(dynsm + OFF_VS);
    f16*   Ps  = (f16*)(dynsm + OFF_PS);
    float* Ost = (float*)dynsm;

    const int tid = threadIdx.x;
    const int wid = tid >> 5;
    const int bh  = blockIdx.y, b = bh >> 4, h = bh & 15;
    const int q0  = blockIdx.x * 128;

    const f16* qg  = g_qh + (size_t)(b*Sq + q0) * Eq + h*DKq;
    const f16* kgb = g_kh + (size_t)b * Sq * Eq + h*DKq;
    const f16* vgb = g_vh + (size_t)b * Sq * Eq + h*DKq;

    #pragma unroll
    for (int it = 0; it < 4; it++) {
        int c = tid + it*256;
        int r = c >> 3, c8 = (c & 7) * 8;
        *(uint4*)&Qs[r*QS_LD + c8] = *(const uint4*)(qg + (size_t)r * Eq + c8);
    }
    #pragma unroll
    for (int it = 0; it < 8; it++) {
        int idx = tid + it*256;
        int st  = idx >> 10;
        int rem = idx & 1023;
        int r   = rem >> 4, c = 64 + (rem & 15);
        Vs[(st*64 + r)*VS_LD + c] = (c == 64) ? __float2half(1.0f) : __float2half(0.0f);
    }

    const uint32_t ksb = (uint32_t)__cvta_generic_to_shared(Ks);
    const uint32_t vsb = (uint32_t)__cvta_generic_to_shared(Vs);
    int kr[2], kc[2];
    #pragma unroll
    for (int i = 0; i < 2; i++) {
        int c = tid + i*256;
        kr[i] = c >> 3; kc[i] = (c & 7) * 8;
    }
    const uint32_t stgK = 64*KS_LD*2, stgV = 64*VS_LD*2;

    wmma::fragment<wmma::accumulator, 16, 16, 16, float> Of[5];
    #pragma unroll
    for (int nf = 0; nf < 5; nf++) wmma::fill_fragment(Of[nf], 0.0f);

    #pragma unroll
    for (int i = 0; i < 2; i++) {
        cpa16(ksb + (uint32_t)(kr[i]*KS_LD + kc[i])*2, kgb + (size_t)kr[i]*Eq + kc[i]);
        cpa16(vsb + (uint32_t)(kr[i]*VS_LD + kc[i])*2, vgb + (size_t)kr[i]*Eq + kc[i]);
    }
    asm volatile("cp.async.commit_group;\n");

    __syncthreads();
    wmma::fragment<wmma::matrix_a, 16, 16, 16, f16, wmma::row_major> qf[4];
    #pragma unroll
    for (int kf = 0; kf < 4; kf++)
        wmma::load_matrix_sync(qf[kf], &Qs[(wid*16)*QS_LD + kf*16], QS_LD);

    const int NT = Sq / 64;
    for (int kt = 0; kt < NT; kt++) {
        const int cur = kt & 1;
        __syncthreads();
        if (kt + 1 < NT) {
            const int nxt = (kt + 1) & 1;
            const size_t go = (size_t)(kt + 1) * 64 * Eq;
            #pragma unroll
            for (int i = 0; i < 2; i++) {
                cpa16(ksb + nxt*stgK + (uint32_t)(kr[i]*KS_LD + kc[i])*2,
                      kgb + go + (size_t)kr[i]*Eq + kc[i]);
                cpa16(vsb + nxt*stgV + (uint32_t)(kr[i]*VS_LD + kc[i])*2,
                      vgb + go + (size_t)kr[i]*Eq + kc[i]);
            }
            asm volatile("cp.async.commit_group;\n");
            asm volatile("cp.async.wait_group 1;\n");
        } else {
            asm volatile("cp.async.wait_group 0;\n");
        }
        __syncthreads();
        const f16* Kc = Ks + cur * (64*KS_LD);
        const f16* Vc = Vs + cur * (64*VS_LD);

        wmma::fragment<wmma::accumulator, 16, 16, 16, f16> Sacc[4];
        #pragma unroll
        for (int nf = 0; nf < 4; nf++) wmma::fill_fragment(Sacc[nf], __float2half(0.0f));
        #pragma unroll
        for (int kf = 0; kf < 4; kf++) {
            #pragma unroll
            for (int nf = 0; nf < 4; nf++) {
                wmma::fragment<wmma::matrix_b, 16, 16, 16, f16, wmma::col_major> bfr;
                wmma::load_matrix_sync(bfr, &Kc[(nf*16)*KS_LD + kf*16], KS_LD);
                wmma::mma_sync(Sacc[nf], qf[kf], bfr, Sacc[nf]);
            }
        }
        // P = exp2(S): packed half2 MUFU (2 elems/op)
        #pragma unroll
        for (int nf = 0; nf < 4; nf++) {
            __half2* px = reinterpret_cast<__half2*>(&Sacc[nf].x[0]);
            #pragma unroll
            for (int t = 0; t < 4; t++) px[t] = h2exp2(px[t]);
            wmma::store_matrix_sync(&Ps[(wid*16)*PS_LD + nf*16], Sacc[nf], PS_LD,
                                    wmma::mem_row_major);
        }
        #pragma unroll
        for (int kf = 0; kf < 4; kf++) {
            wmma::fragment<wmma::matrix_a, 16, 16, 16, f16, wmma::row_major> pa;
            wmma::load_matrix_sync(pa, &Ps[(wid*16)*PS_LD + kf*16], PS_LD);
            #pragma unroll
            for (int nf = 0; nf < 5; nf++) {
                wmma::fragment<wmma::matrix_b, 16, 16, 16, f16, wmma::row_major> vb;
                wmma::load_matrix_sync(vb, &Vc[(kf*16)*VS_LD + nf*16], VS_LD);
                wmma::mma_sync(Of[nf], pa, vb, Of[nf]);
            }
        }
    }

    __syncthreads();
    #pragma unroll
    for (int nf = 0; nf < 5; nf++)
        wmma::store_matrix_sync(&Ost[(wid*16)*OST_LD + nf*16], Of[nf], OST_LD,
                                wmma::mem_row_major);
    __syncthreads();

    const float cat = g_cattn;
    const int orow = tid >> 1;
    const int ocol = (tid & 1) * 32;
    const float inv = 1.0f / Ost[orow*OST_LD + 64];
    f16* og = g_mixed + (size_t)(b*Sq + q0 + orow) * Eq + h*DKq + ocol;
    #pragma unroll
    for (int j = 0; j < 8; j++) {
        float4 v = *(float4*)&Ost[orow*OST_LD + ocol + j*4];
        v.x *= inv; v.y *= inv; v.z *= inv; v.w *= inv;
        if (ocol == 0 && j == 0) { v.x += cat; v.y += cat; v.z += cat; v.w += cat; }
        __half2* d = (__half2*)(og + j*4);
        d[0] = __floats2half2_rn(v.x, v.y);
        d[1] = __floats2half2_rn(v.z, v.w);
    }
}

// ---------------- fused LN1+LN2 ----------------
__device__ __forceinline__ float block_reduce_sum(float v) {
    __shared__ float sh[8];
    const int tid = threadIdx.x;
    for (int o = 16; o > 0; o >>= 1) v += __shfl_xor_sync(0xffffffffu, v, o);
    if ((tid & 31) == 0) sh[tid >> 5] = v;
    __syncthreads();
    float r;
    if (tid == 0) {
        r = sh[0];
        for (int i = 1; i < 8; i++) r += sh[i];
        sh[0] = r;
    }
    __syncthreads();
    r = sh[0];
    __syncthreads();
    return r;
}

__global__ __launch_bounds__(256)
void ln12_kernel(const float* __restrict__ x, float* __restrict__ out,
                 const float* __restrict__ g1, const float* __restrict__ b1v,
                 const float* __restrict__ g2, const float* __restrict__ b2v) {
    const size_t row = blockIdx.x;
    const int tid = threadIdx.x;
    float4 xv = *(const float4*)(x + row * Eq + tid*4);
    float4 av = *(const float4*)(g_attnout + row * Eq + tid*4);
    float t[4] = { xv.x+av.x, xv.y+av.y, xv.z+av.z, xv.w+av.w };
    float mean = block_reduce_sum(t[0]+t[1]+t[2]+t[3]) * (1.0f / Eq);
    float vs = 0.f;
    #pragma unroll
    for (int i = 0; i < 4; i++) { float d = t[i] - mean; vs += d*d; }
    float var = block_reduce_sum(vs) * (1.0f / Eq);
    float inv = rsqrtf(var + LN_EPS);
    float4 fv = *(const float4*)(g_ffnvec + tid*4);
    float u[4];
    #pragma unroll
    for (int i = 0; i < 4; i++) {
        int c = tid*4 + i;
        float x1 = (t[i] - mean) * inv * g1[c] + b1v[c];
        u[i] = x1 + ((const float*)&fv)[i];
    }
    float mean2 = block_reduce_sum(u[0]+u[1]+u[2]+u[3]) * (1.0f / Eq);
    float vs2 = 0.f;
    #pragma unroll
    for (int i = 0; i < 4; i++) { float d = u[i] - mean2; vs2 += d*d; }
    float var2 = block_reduce_sum(vs2) * (1.0f / Eq);
    float inv2 = rsqrtf(var2 + LN_EPS);
    float o[4];
    #pragma unroll
    for (int i = 0; i < 4; i++) {
        int c = tid*4 + i;
        o[i] = (u[i] - mean2) * inv2 * g2[c] + b2v[c];
    }
    *(float4*)(out + row * Eq + tid*4) = make_float4(o[0], o[1], o[2], o[3]);
}

// ---------------- launch ----------------
extern "C" void kernel_launch(void* const* d_in, const int* in_sizes, int n_in,
                              void* d_out, int out_size) {
    const float* x    = (const float*)d_in[0];
    const float* wq   = (const float*)d_in[1];
    const float* wk   = (const float*)d_in[2];
    const float* wv   = (const float*)d_in[3];
    const float* wo   = (const float*)d_in[4];
    // d_in[5] = w1, d_in[6] = b1 : mathematically dead (never consumed)
    const float* w2   = (const float*)d_in[7];
    const float* b2   = (const float*)d_in[8];
    const float* qpa  = (const float*)d_in[9];
    const float* qpf  = (const float*)d_in[10];
    const float* ln1g = (const float*)d_in[11];
    const float* ln1b = (const float*)d_in[12];
    const float* ln2g = (const float*)d_in[13];
    const float* ln2b = (const float*)d_in[14];
    float* out = (float*)d_out;

    f16* pxh;
    cudaGetSymbolAddress((void**)&pxh, g_xh);

    cudaFuncSetAttribute(flash_f16,
                         cudaFuncAttributeMaxDynamicSharedMemorySize, SMEM_FLASH);
    cudaFuncSetAttribute(gemm_qkv,
                         cudaFuncAttributeMaxDynamicSharedMemorySize, G_SMEM);
    cudaFuncSetAttribute(gemm_wo,
                         cudaFuncAttributeMaxDynamicSharedMemorySize, G_SMEM);

    prep_kernel<<<1, 1024>>>(qpa, qpf, w2, b2);

    conv_x_kernel<<<(Mq*Eq/4 + 255)/256, 256>>>(x, pxh, Mq*Eq/4);
    conv_w_kernel<<<dim3((Eq*Eq/4 + 255)/256, 4), 256>>>(wq, wk, wv, wo);

    const float qsc = 0.125f * LOG2E;
    gemm_qkv<<<dim3(24, Mq/128), 128, G_SMEM>>>(qsc);

    flash_f16<<<dim3(Sq/128, BHq), 256, SMEM_FLASH>>>();

    gemm_wo<<<dim3(Eq/128, Mq/128), 128, G_SMEM>>>();

    ln12_kernel<<<Mq, 256>>>(x, out, ln1g, ln1b, ln2g, ln2b);
}

// round 11
// speedup vs baseline: 1.0575x; 1.0575x over previous
#include <cuda_runtime.h>
#include <cuda_fp16.h>
#include <mma.h>
#include <math.h>
#include <stdint.h>

using namespace nvcuda;

// Problem dims
#define Bq   2
#define Sq   2048
#define Eq   1024
#define Hq   16
#define DKq  64
#define Mq   (Bq*Sq)    // 4096
#define BHq  (Bq*Hq)    // 32
#define LN_EPS 1e-5f
#define LOG2E 1.442695040888963f

typedef __half f16;

// ---------------- scratch (device globals; no allocs allowed) ----------------
__device__ f16   g_xh[Mq*Eq];
__device__ f16   g_wqh[Eq*Eq];
__device__ f16   g_wkh[Eq*Eq];
__device__ f16   g_wvh[Eq*Eq];
__device__ f16   g_woh[Eq*Eq];
__device__ f16   g_qh[Mq*Eq];           // q f16, pre-scaled by 0.125*log2e
__device__ f16   g_kh[Mq*Eq];
__device__ f16   g_vh[Mq*Eq];
__device__ f16   g_mixed[Mq*Eq];        // attention result (+c_attn), f16
__device__ float g_attnout[Mq*Eq];      // mixed @ wo, fp32
__device__ float g_ffnvec[Eq];          // data-free FFN output vector
__device__ float g_cattn;

__device__ __forceinline__ void cpa16(uint32_t dst, const void* src) {
    asm volatile("cp.async.cg.shared.global [%0], [%1], 16;\n" :: "r"(dst), "l"(src));
}

// ---------------- prep: quantum scalars + collapsed FFN vector ----------------
__global__ void prep_kernel(const float* __restrict__ qp_attn,
                            const float* __restrict__ qp_ffn,
                            const float* __restrict__ w2,
                            const float* __restrict__ b2) {
    int e = threadIdx.x;
    if (e == 0) g_cattn = cosf(qp_attn[0] + qp_attn[1]);
    float cf = cosf(qp_ffn[0] + qp_ffn[1]);
    float rf = cf > 0.f ? cf : 0.f;   // relu
    if (e < Eq) {
        g_ffnvec[e] = rf * (w2[e] + w2[Eq + e] + w2[2*Eq + e] + w2[3*Eq + e]) + b2[e];
    }
}

// ---------------- fp32 -> f16 conversion ------------------------
__global__ __launch_bounds__(256)
void conv_x_kernel(const float* __restrict__ s, f16* __restrict__ d, int n4) {
    int i = blockIdx.x * blockDim.x + threadIdx.x;
    if (i < n4) {
        float4 v = ((const float4*)s)[i];
        ((__half2*)d)[2*i]   = __floats2half2_rn(v.x, v.y);
        ((__half2*)d)[2*i+1] = __floats2half2_rn(v.z, v.w);
    }
}
__global__ __launch_bounds__(256)
void conv_w_kernel(const float* __restrict__ wq, const float* __restrict__ wk,
                   const float* __restrict__ wv, const float* __restrict__ wo) {
    int i = blockIdx.x * blockDim.x + threadIdx.x;
    const int n4 = Eq*Eq/4;
    if (i >= n4) return;
    const float* s; f16* d;
    switch (blockIdx.y) {
        case 0:  s = wq; d = g_wqh; break;
        case 1:  s = wk; d = g_wkh; break;
        case 2:  s = wv; d = g_wvh; break;
        default: s = wo; d = g_woh; break;
    }
    float4 v = ((const float4*)s)[i];
    ((__half2*)d)[2*i]   = __floats2half2_rn(v.x, v.y);
    ((__half2*)d)[2*i+1] = __floats2half2_rn(v.z, v.w);
}

// ---------------- f16 WMMA GEMM core (cp.async 3-stage, BK=32) -----------------
// Block 128x128, BK=32, 128 threads = 4 warps (2m x 2n), warp tile 64x64.
// R8's proven strides; 3 stages, ONE syncthreads per iteration, prefetch depth 2.
#define AS_LD 40
#define BS_LD 136
#define A_STG (128*AS_LD)          // 5120 halves / stage
#define B_STG (32*BS_LD)           // 4352 halves / stage
#define G_OFF_B (3*A_STG*2)        // 30720 bytes
#define G_SMEM  (G_OFF_B + 3*B_STG*2)   // 56832 bytes
#define STG_LD 20                  // epilogue staging stride (floats), mult of 4

struct GemmCore {
    wmma::fragment<wmma::accumulator, 16, 16, 16, float> acc[4][4];

    __device__ __forceinline__ void run(const f16* A, const f16* B,
                                        int m0, int n0, char* dynsm, int tid) {
        const int wid = tid >> 5;
        const int wm  = wid & 1, wn = wid >> 1;
        f16* As = (f16*)dynsm;
        f16* Bs = (f16*)(dynsm + G_OFF_B);
        const uint32_t asb = (uint32_t)__cvta_generic_to_shared(As);
        const uint32_t bsb = (uint32_t)__cvta_generic_to_shared(Bs);

        const f16* aSrc[4]; uint32_t aDst[4];
        const f16* bSrc[4]; uint32_t bDst[4];
        #pragma unroll
        for (int i = 0; i < 4; i++) {
            int c = tid + i*128;
            int arow = c >> 2, ac8 = (c & 3) * 8;
            aSrc[i] = A + (size_t)(m0 + arow) * Eq + ac8;
            aDst[i] = asb + (uint32_t)(arow*AS_LD + ac8) * 2;
            int brow = c >> 4, bc8 = (c & 15) * 8;
            bSrc[i] = B + (size_t)brow * Eq + n0 + bc8;
            bDst[i] = bsb + (uint32_t)(brow*BS_LD + bc8) * 2;
        }
        #pragma unroll
        for (int mi = 0; mi < 4; mi++)
            #pragma unroll
            for (int ni = 0; ni < 4; ni++)
                wmma::fill_fragment(acc[mi][ni], 0.0f);

        const int niter = Eq / 32;   // 32
        // preload stages 0 and 1 (one commit group each)
        #pragma unroll
        for (int s = 0; s < 2; s++) {
            const uint32_t ao = (uint32_t)(s * A_STG) * 2;
            const uint32_t bo = (uint32_t)(s * B_STG) * 2;
            #pragma unroll
            for (int i = 0; i < 4; i++) cpa16(aDst[i] + ao, aSrc[i] + s*32);
            #pragma unroll
            for (int i = 0; i < 4; i++) cpa16(bDst[i] + bo, bSrc[i] + (size_t)s*32*Eq);
            asm volatile("cp.async.commit_group;\n");
        }

        int cur = 0, pf = 2;
        for (int kb = 0; kb < niter; kb++) {
            // stage 'cur' ready (own copies); then block-wide visibility + prev compute done
            if (kb < niter - 1) asm volatile("cp.async.wait_group 1;\n" ::: "memory");
            else                asm volatile("cp.async.wait_group 0;\n" ::: "memory");
            __syncthreads();
            // prefetch into stage 'pf' (= stage used in iter kb-1; free after the sync)
            if (kb + 2 < niter) {
                const uint32_t ao = (uint32_t)(pf * A_STG) * 2;
                const uint32_t bo = (uint32_t)(pf * B_STG) * 2;
                const int koffA = (kb + 2) * 32;
                const size_t koffB = (size_t)(kb + 2) * 32 * Eq;
                #pragma unroll
                for (int i = 0; i < 4; i++) cpa16(aDst[i] + ao, aSrc[i] + koffA);
                #pragma unroll
                for (int i = 0; i < 4; i++) cpa16(bDst[i] + bo, bSrc[i] + koffB);
                asm volatile("cp.async.commit_group;\n");
            }
            const f16* Ac = As + cur * A_STG;
            const f16* Bc = Bs + cur * B_STG;
            #pragma unroll
            for (int ks = 0; ks < 2; ks++) {
                wmma::fragment<wmma::matrix_a, 16, 16, 16, f16, wmma::row_major> af[4];
                wmma::fragment<wmma::matrix_b, 16, 16, 16, f16, wmma::row_major> bfr[4];
                #pragma unroll
                for (int mi = 0; mi < 4; mi++)
                    wmma::load_matrix_sync(af[mi], Ac + (wm*64 + mi*16)*AS_LD + ks*16, AS_LD);
                #pragma unroll
                for (int ni = 0; ni < 4; ni++)
                    wmma::load_matrix_sync(bfr[ni], Bc + (ks*16)*BS_LD + wn*64 + ni*16, BS_LD);
                #pragma unroll
                for (int mi = 0; mi < 4; mi++)
                    #pragma unroll
                    for (int ni = 0; ni < 4; ni++)
                        wmma::mma_sync(acc[mi][ni], af[mi], bfr[ni], acc[mi][ni]);
            }
            cur = (cur == 2) ? 0 : cur + 1;
            pf  = (pf  == 2) ? 0 : pf  + 1;
        }
        __syncthreads();   // smem free for epilogue staging
    }
};

// fused QKV projection: grid (24, 32); blockIdx.x selects tensor + n-block
__global__ __launch_bounds__(128, 2)
void gemm_qkv(float qscale) {
    extern __shared__ char dynsm[];
    const int tid = threadIdx.x;
    const int wid = tid >> 5, lane = tid & 31;
    const int wm  = wid & 1, wn = wid >> 1;
    const int t   = blockIdx.x >> 3;           // 0=q, 1=k, 2=v
    const int n0  = (blockIdx.x & 7) * 128;
    const int m0  = blockIdx.y * 128;
    const f16* B = (t == 0) ? g_wqh : (t == 1) ? g_wkh : g_wvh;
    f16*       C = (t == 0) ? g_qh  : (t == 1) ? g_kh  : g_vh;
    const float scale = (t == 0) ? qscale : 1.0f;

    GemmCore core;
    core.run(g_xh, B, m0, n0, dynsm, tid);

    float* stgw = ((float*)dynsm) + wid * (16*STG_LD);
    const int srow = lane >> 1, scol = (lane & 1) * 8;
    #pragma unroll
    for (int mi = 0; mi < 4; mi++) {
        #pragma unroll
        for (int ni = 0; ni < 4; ni++) {
            #pragma unroll
            for (int tt = 0; tt < core.acc[mi][ni].num_elements; tt++)
                core.acc[mi][ni].x[tt] *= scale;
            wmma::store_matrix_sync(stgw, core.acc[mi][ni], STG_LD, wmma::mem_row_major);
            __syncwarp();
            const float* sp = stgw + srow*STG_LD + scol;
            union { f16 h[8]; uint4 u; } tmp;
            #pragma unroll
            for (int j = 0; j < 8; j += 2) {
                __half2 p = __floats2half2_rn(sp[j], sp[j+1]);
                tmp.h[j] = p.x;  tmp.h[j+1] = p.y;
            }
            f16* cp = C + (size_t)(m0 + wm*64 + mi*16 + srow) * Eq
                        + n0 + wn*64 + ni*16 + scol;
            *(uint4*)cp = tmp.u;
            __syncwarp();
        }
    }
}

// wo projection: fp32 out
__global__ __launch_bounds__(128, 2)
void gemm_wo() {
    extern __shared__ char dynsm[];
    const int tid = threadIdx.x;
    const int wid = tid >> 5;
    const int wm  = wid & 1, wn = wid >> 1;
    const int m0  = blockIdx.y * 128, n0 = blockIdx.x * 128;

    GemmCore core;
    core.run(g_mixed, g_woh, m0, n0, dynsm, tid);

    #pragma unroll
    for (int mi = 0; mi < 4; mi++)
        #pragma unroll
        for (int ni = 0; ni < 4; ni++)
            wmma::store_matrix_sync(g_attnout + (size_t)(m0 + wm*64 + mi*16) * Eq
                                    + n0 + wn*64 + ni*16,
                                    core.acc[mi][ni], Eq, wmma::mem_row_major);
}

// ---------------- fused flash attention (f16, Q-tile 128, key-tile 64) --------
// 256 threads (8 warps). Q frags in registers. Half-accum QK^T -> h2exp2 ->
// P f16 (warp-private). Row sums via ones-column in V. 3-stage K/V pipeline,
// ONE syncthreads per key tile, prefetch depth 2.
#define QS_LD 72
#define KS_LD 72
#define VS_LD 88
#define PS_LD 72
#define OST_LD 84
#define KSTG (64*KS_LD)            // halves per K stage
#define VSTG (64*VS_LD)            // halves per V stage
#define OFF_QS 0
#define OFF_KS (128*QS_LD*2)                    // 18432
#define OFF_VS (OFF_KS + 3*KSTG*2)              // +27648 = 46080
#define OFF_PS (OFF_VS + 3*VSTG*2)              // +33792 = 79872
#define SMEM_FLASH (OFF_PS + 128*PS_LD*2)       // +18432 = 98304

__global__ __launch_bounds__(256)
void flash_f16() {
    extern __shared__ char dynsm[];
    f16*   Qs  = (f16*)(dynsm + OFF_QS);
    f16*   Ks  = (f16*)(dynsm + OFF_KS);
    f16*   Vs  = (f16*)(dynsm + OFF_VS);
    f16*   Ps  = (f16*)(dynsm + OFF_PS);
    float* Ost = (float*)dynsm;

    const int tid = threadIdx.x;
    const int wid = tid >> 5;
    const int bh  = blockIdx.y, b = bh >> 4, h = bh & 15;
    const int q0  = blockIdx.x * 128;

    const f16* qg  = g_qh + (size_t)(b*Sq + q0) * Eq + h*DKq;
    const f16* kgb = g_kh + (size_t)b * Sq * Eq + h*DKq;
    const f16* vgb = g_vh + (size_t)b * Sq * Eq + h*DKq;

    // load Q: 128 rows x 64 halves
    #pragma unroll
    for (int it = 0; it < 4; it++) {
        int c = tid + it*256;
        int r = c >> 3, c8 = (c & 7) * 8;
        *(uint4*)&Qs[r*QS_LD + c8] = *(const uint4*)(qg + (size_t)r * Eq + c8);
    }
    // ones-block of V (cols 64..79, all 3 stages): col 64 = 1, else 0
    for (int idx = tid; idx < 3*1024; idx += 256) {
        int st  = idx >> 10;
        int rem = idx & 1023;
        int r   = rem >> 4, c = 64 + (rem & 15);
        Vs[st*VSTG + r*VS_LD + c] = (c == 64) ? __float2half(1.0f) : __float2half(0.0f);
    }

    const uint32_t ksb = (uint32_t)__cvta_generic_to_shared(Ks);
    const uint32_t vsb = (uint32_t)__cvta_generic_to_shared(Vs);
    int kr[2], kc[2];
    #pragma unroll
    for (int i = 0; i < 2; i++) {
        int c = tid + i*256;
        kr[i] = c >> 3; kc[i] = (c & 7) * 8;
    }

    wmma::fragment<wmma::accumulator, 16, 16, 16, float> Of[5];
    #pragma unroll
    for (int nf = 0; nf < 5; nf++) wmma::fill_fragment(Of[nf], 0.0f);

    // preload key tiles 0 and 1 into stages 0,1 (one commit each)
    #pragma unroll
    for (int s = 0; s < 2; s++) {
        const size_t go = (size_t)s * 64 * Eq;
        #pragma unroll
        for (int i = 0; i < 2; i++) {
            cpa16(ksb + (uint32_t)(s*KSTG + kr[i]*KS_LD + kc[i])*2,
                  kgb + go + (size_t)kr[i]*Eq + kc[i]);
            cpa16(vsb + (uint32_t)(s*VSTG + kr[i]*VS_LD + kc[i])*2,
                  vgb + go + (size_t)kr[i]*Eq + kc[i]);
        }
        asm volatile("cp.async.commit_group;\n");
    }

    __syncthreads();   // Qs + ones-block visible
    wmma::fragment<wmma::matrix_a, 16, 16, 16, f16, wmma::row_major> qf[4];
    #pragma unroll
    for (int kf = 0; kf < 4; kf++)
        wmma::load_matrix_sync(qf[kf], &Qs[(wid*16)*QS_LD + kf*16], QS_LD);

    const int NT = Sq / 64;   // 32
    int cur = 0, pf = 2;
    for (int kt = 0; kt < NT; kt++) {
        if (kt < NT - 1) asm volatile("cp.async.wait_group 1;\n" ::: "memory");
        else             asm volatile("cp.async.wait_group 0;\n" ::: "memory");
        __syncthreads();
        if (kt + 2 < NT) {
            const size_t go = (size_t)(kt + 2) * 64 * Eq;
            #pragma unroll
            for (int i = 0; i < 2; i++) {
                cpa16(ksb + (uint32_t)(pf*KSTG + kr[i]*KS_LD + kc[i])*2,
                      kgb + go + (size_t)kr[i]*Eq + kc[i]);
                cpa16(vsb + (uint32_t)(pf*VSTG + kr[i]*VS_LD + kc[i])*2,
                      vgb + go + (size_t)kr[i]*Eq + kc[i]);
            }
            asm volatile("cp.async.commit_group;\n");
        }
        const f16* Kc = Ks + cur * KSTG;
        const f16* Vc = Vs + cur * VSTG;

        // S = Q @ K^T, half accumulators
        wmma::fragment<wmma::accumulator, 16, 16, 16, f16> Sacc[4];
        #pragma unroll
        for (int nf = 0; nf < 4; nf++) wmma::fill_fragment(Sacc[nf], __float2half(0.0f));
        #pragma unroll
        for (int kf = 0; kf < 4; kf++) {
            #pragma unroll
            for (int nf = 0; nf < 4; nf++) {
                wmma::fragment<wmma::matrix_b, 16, 16, 16, f16, wmma::col_major> bfr;
                wmma::load_matrix_sync(bfr, &Kc[(nf*16)*KS_LD + kf*16], KS_LD);
                wmma::mma_sync(Sacc[nf], qf[kf], bfr, Sacc[nf]);
            }
        }
        // P = exp2(S): packed half2 MUFU
        #pragma unroll
        for (int nf = 0; nf < 4; nf++) {
            __half2* px = reinterpret_cast<__half2*>(&Sacc[nf].x[0]);
            #pragma unroll
            for (int t = 0; t < 4; t++) px[t] = h2exp2(px[t]);
            wmma::store_matrix_sync(&Ps[(wid*16)*PS_LD + nf*16], Sacc[nf], PS_LD,
                                    wmma::mem_row_major);
        }
        // O += P @ V (5th n-frag = row sums via ones column)
        #pragma unroll
        for (int kf = 0; kf < 4; kf++) {
            wmma::fragment<wmma::matrix_a, 16, 16, 16, f16, wmma::row_major> pa;
            wmma::load_matrix_sync(pa, &Ps[(wid*16)*PS_LD + kf*16], PS_LD);
            #pragma unroll
            for (int nf = 0; nf < 5; nf++) {
                wmma::fragment<wmma::matrix_b, 16, 16, 16, f16, wmma::row_major> vb;
                wmma::load_matrix_sync(vb, &Vc[(kf*16)*VS_LD + nf*16], VS_LD);
                wmma::mma_sync(Of[nf], pa, vb, Of[nf]);
            }
        }
        cur = (cur == 2) ? 0 : cur + 1;
        pf  = (pf  == 2) ? 0 : pf  + 1;
    }

    __syncthreads();
    #pragma unroll
    for (int nf = 0; nf < 5; nf++)
        wmma::store_matrix_sync(&Ost[(wid*16)*OST_LD + nf*16], Of[nf], OST_LD,
                                wmma::mem_row_major);
    __syncthreads();

    const float cat = g_cattn;
    const int orow = tid >> 1;
    const int ocol = (tid & 1) * 32;
    const float inv = 1.0f / Ost[orow*OST_LD + 64];
    f16* og = g_mixed + (size_t)(b*Sq + q0 + orow) * Eq + h*DKq + ocol;
    #pragma unroll
    for (int j = 0; j < 8; j++) {
        float4 v = *(float4*)&Ost[orow*OST_LD + ocol + j*4];
        v.x *= inv; v.y *= inv; v.z *= inv; v.w *= inv;
        if (ocol == 0 && j == 0) { v.x += cat; v.y += cat; v.z += cat; v.w += cat; }
        __half2* d = (__half2*)(og + j*4);
        d[0] = __floats2half2_rn(v.x, v.y);
        d[1] = __floats2half2_rn(v.z, v.w);
    }
}

// ---------------- fused LN1+LN2 ----------------
__device__ __forceinline__ float block_reduce_sum(float v) {
    __shared__ float sh[8];
    const int tid = threadIdx.x;
    for (int o = 16; o > 0; o >>= 1) v += __shfl_xor_sync(0xffffffffu, v, o);
    if ((tid & 31) == 0) sh[tid >> 5] = v;
    __syncthreads();
    float r;
    if (tid == 0) {
        r = sh[0];
        for (int i = 1; i < 8; i++) r += sh[i];
        sh[0] = r;
    }
    __syncthreads();
    r = sh[0];
    __syncthreads();
    return r;
}

__global__ __launch_bounds__(256)
void ln12_kernel(const float* __restrict__ x, float* __restrict__ out,
                 const float* __restrict__ g1, const float* __restrict__ b1v,
                 const float* __restrict__ g2, const float* __restrict__ b2v) {
    const size_t row = blockIdx.x;
    const int tid = threadIdx.x;
    float4 xv = *(const float4*)(x + row * Eq + tid*4);
    float4 av = *(const float4*)(g_attnout + row * Eq + tid*4);
    float t[4] = { xv.x+av.x, xv.y+av.y, xv.z+av.z, xv.w+av.w };
    float mean = block_reduce_sum(t[0]+t[1]+t[2]+t[3]) * (1.0f / Eq);
    float vs = 0.f;
    #pragma unroll
    for (int i = 0; i < 4; i++) { float d = t[i] - mean; vs += d*d; }
    float var = block_reduce_sum(vs) * (1.0f / Eq);
    float inv = rsqrtf(var + LN_EPS);
    float4 fv = *(const float4*)(g_ffnvec + tid*4);
    float u[4];
    #pragma unroll
    for (int i = 0; i < 4; i++) {
        int c = tid*4 + i;
        float x1 = (t[i] - mean) * inv * g1[c] + b1v[c];
        u[i] = x1 + ((const float*)&fv)[i];
    }
    float mean2 = block_reduce_sum(u[0]+u[1]+u[2]+u[3]) * (1.0f / Eq);
    float vs2 = 0.f;
    #pragma unroll
    for (int i = 0; i < 4; i++) { float d = u[i] - mean2; vs2 += d*d; }
    float var2 = block_reduce_sum(vs2) * (1.0f / Eq);
    float inv2 = rsqrtf(var2 + LN_EPS);
    float o[4];
    #pragma unroll
    for (int i = 0; i < 4; i++) {
        int c = tid*4 + i;
        o[i] = (u[i] - mean2) * inv2 * g2[c] + b2v[c];
    }
    *(float4*)(out + row * Eq + tid*4) = make_float4(o[0], o[1], o[2], o[3]);
}

// ---------------- launch ----------------
extern "C" void kernel_launch(void* const* d_in, const int* in_sizes, int n_in,
                              void* d_out, int out_size) {
    const float* x    = (const float*)d_in[0];
    const float* wq   = (const float*)d_in[1];
    const float* wk   = (const float*)d_in[2];
    const float* wv   = (const float*)d_in[3];
    const float* wo   = (const float*)d_in[4];
    // d_in[5] = w1, d_in[6] = b1 : mathematically dead (never consumed)
    const float* w2   = (const float*)d_in[7];
    const float* b2   = (const float*)d_in[8];
    const float* qpa  = (const float*)d_in[9];
    const float* qpf  = (const float*)d_in[10];
    const float* ln1g = (const float*)d_in[11];
    const float* ln1b = (const float*)d_in[12];
    const float* ln2g = (const float*)d_in[13];
    const float* ln2b = (const float*)d_in[14];
    float* out = (float*)d_out;

    f16* pxh;
    cudaGetSymbolAddress((void**)&pxh, g_xh);

    cudaFuncSetAttribute(flash_f16,
                         cudaFuncAttributeMaxDynamicSharedMemorySize, SMEM_FLASH);
    cudaFuncSetAttribute(gemm_qkv,
                         cudaFuncAttributeMaxDynamicSharedMemorySize, G_SMEM);
    cudaFuncSetAttribute(gemm_wo,
                         cudaFuncAttributeMaxDynamicSharedMemorySize, G_SMEM);

    prep_kernel<<<1, 1024>>>(qpa, qpf, w2, b2);

    conv_x_kernel<<<(Mq*Eq/4 + 255)/256, 256>>>(x, pxh, Mq*Eq/4);
    conv_w_kernel<<<dim3((Eq*Eq/4 + 255)/256, 4), 256>>>(wq, wk, wv, wo);

    const float qsc = 0.125f * LOG2E;
    gemm_qkv<<<dim3(24, Mq/128), 128, G_SMEM>>>(qsc);

    flash_f16<<<dim3(Sq/128, BHq), 256, SMEM_FLASH>>>();

    gemm_wo<<<dim3(Eq/128, Mq/128), 128, G_SMEM>>>();

    ln12_kernel<<<Mq, 256>>>(x, out, ln1g, ln1b, ln2g, ln2b);
}

// round 12
// speedup vs baseline: 1.0583x; 1.0007x over previous
#include <cuda_runtime.h>
#include <cuda_fp16.h>
#include <mma.h>
#include <math.h>
#include <stdint.h>

using namespace nvcuda;

// Problem dims
#define Bq   2
#define Sq   2048
#define Eq   1024
#define Hq   16
#define DKq  64
#define Mq   (Bq*Sq)    // 4096
#define BHq  (Bq*Hq)    // 32
#define LN_EPS 1e-5f
#define LOG2E 1.442695040888963f

typedef __half f16;

// ---------------- scratch (device globals; no allocs allowed) ----------------
__device__ f16   g_xh[Mq*Eq];
__device__ f16   g_wqh[Eq*Eq];
__device__ f16   g_wkh[Eq*Eq];
__device__ f16   g_wvh[Eq*Eq];
__device__ f16   g_woh[Eq*Eq];
__device__ f16   g_qh[Mq*Eq];           // q f16, pre-scaled by 0.125*log2e
__device__ f16   g_kh[Mq*Eq];
__device__ f16   g_vh[Mq*Eq];
__device__ f16   g_mixed[Mq*Eq];        // attention result (+c_attn), f16
__device__ float g_attnout[Mq*Eq];      // mixed @ wo, fp32
__device__ float g_ffnvec[Eq];          // data-free FFN output vector
__device__ float g_cattn;

__device__ __forceinline__ void cpa16(uint32_t dst, const void* src) {
    asm volatile("cp.async.cg.shared.global [%0], [%1], 16;\n" :: "r"(dst), "l"(src));
}

// ---------------- prep: quantum scalars + collapsed FFN vector ----------------
__global__ void prep_kernel(const float* __restrict__ qp_attn,
                            const float* __restrict__ qp_ffn,
                            const float* __restrict__ w2,
                            const float* __restrict__ b2) {
    int e = threadIdx.x;
    if (e == 0) g_cattn = cosf(qp_attn[0] + qp_attn[1]);
    float cf = cosf(qp_ffn[0] + qp_ffn[1]);
    float rf = cf > 0.f ? cf : 0.f;   // relu
    if (e < Eq) {
        g_ffnvec[e] = rf * (w2[e] + w2[Eq + e] + w2[2*Eq + e] + w2[3*Eq + e]) + b2[e];
    }
}

// ---------------- fp32 -> f16 conversion ------------------------
__global__ __launch_bounds__(256)
void conv_x_kernel(const float* __restrict__ s, f16* __restrict__ d, int n4) {
    int i = blockIdx.x * blockDim.x + threadIdx.x;
    if (i < n4) {
        float4 v = ((const float4*)s)[i];
        ((__half2*)d)[2*i]   = __floats2half2_rn(v.x, v.y);
        ((__half2*)d)[2*i+1] = __floats2half2_rn(v.z, v.w);
    }
}
__global__ __launch_bounds__(256)
void conv_w_kernel(const float* __restrict__ wq, const float* __restrict__ wk,
                   const float* __restrict__ wv, const float* __restrict__ wo) {
    int i = blockIdx.x * blockDim.x + threadIdx.x;
    const int n4 = Eq*Eq/4;
    if (i >= n4) return;
    const float* s; f16* d;
    switch (blockIdx.y) {
        case 0:  s = wq; d = g_wqh; break;
        case 1:  s = wk; d = g_wkh; break;
        case 2:  s = wv; d = g_wvh; break;
        default: s = wo; d = g_woh; break;
    }
    float4 v = ((const float4*)s)[i];
    ((__half2*)d)[2*i]   = __floats2half2_rn(v.x, v.y);
    ((__half2*)d)[2*i+1] = __floats2half2_rn(v.z, v.w);
}

// ---------------- f16 WMMA GEMM core (cp.async 3-stage, BK=32) -----------------
// Block 128x128, BK=32, 128 threads = 4 warps (2m x 2n), warp tile 64x64.
#define AS_LD 40
#define BS_LD 136
#define A_STG (128*AS_LD)
#define B_STG (32*BS_LD)
#define G_OFF_B (3*A_STG*2)
#define G_SMEM  (G_OFF_B + 3*B_STG*2)   // 56832 bytes
#define STG_LD 20

struct GemmCore {
    wmma::fragment<wmma::accumulator, 16, 16, 16, float> acc[4][4];

    __device__ __forceinline__ void run(const f16* A, const f16* B,
                                        int m0, int n0, char* dynsm, int tid) {
        const int wid = tid >> 5;
        const int wm  = wid & 1, wn = wid >> 1;
        f16* As = (f16*)dynsm;
        f16* Bs = (f16*)(dynsm + G_OFF_B);
        const uint32_t asb = (uint32_t)__cvta_generic_to_shared(As);
        const uint32_t bsb = (uint32_t)__cvta_generic_to_shared(Bs);

        const f16* aSrc[4]; uint32_t aDst[4];
        const f16* bSrc[4]; uint32_t bDst[4];
        #pragma unroll
        for (int i = 0; i < 4; i++) {
            int c = tid + i*128;
            int arow = c >> 2, ac8 = (c & 3) * 8;
            aSrc[i] = A + (size_t)(m0 + arow) * Eq + ac8;
            aDst[i] = asb + (uint32_t)(arow*AS_LD + ac8) * 2;
            int brow = c >> 4, bc8 = (c & 15) * 8;
            bSrc[i] = B + (size_t)brow * Eq + n0 + bc8;
            bDst[i] = bsb + (uint32_t)(brow*BS_LD + bc8) * 2;
        }
        #pragma unroll
        for (int mi = 0; mi < 4; mi++)
            #pragma unroll
            for (int ni = 0; ni < 4; ni++)
                wmma::fill_fragment(acc[mi][ni], 0.0f);

        const int niter = Eq / 32;   // 32
        #pragma unroll
        for (int s = 0; s < 2; s++) {
            const uint32_t ao = (uint32_t)(s * A_STG) * 2;
            const uint32_t bo = (uint32_t)(s * B_STG) * 2;
            #pragma unroll
            for (int i = 0; i < 4; i++) cpa16(aDst[i] + ao, aSrc[i] + s*32);
            #pragma unroll
            for (int i = 0; i < 4; i++) cpa16(bDst[i] + bo, bSrc[i] + (size_t)s*32*Eq);
            asm volatile("cp.async.commit_group;\n");
        }

        int cur = 0, pf = 2;
        for (int kb = 0; kb < niter; kb++) {
            if (kb < niter - 1) asm volatile("cp.async.wait_group 1;\n" ::: "memory");
            else                asm volatile("cp.async.wait_group 0;\n" ::: "memory");
            __syncthreads();
            if (kb + 2 < niter) {
                const uint32_t ao = (uint32_t)(pf * A_STG) * 2;
                const uint32_t bo = (uint32_t)(pf * B_STG) * 2;
                const int koffA = (kb + 2) * 32;
                const size_t koffB = (size_t)(kb + 2) * 32 * Eq;
                #pragma unroll
                for (int i = 0; i < 4; i++) cpa16(aDst[i] + ao, aSrc[i] + koffA);
                #pragma unroll
                for (int i = 0; i < 4; i++) cpa16(bDst[i] + bo, bSrc[i] + koffB);
                asm volatile("cp.async.commit_group;\n");
            }
            const f16* Ac = As + cur * A_STG;
            const f16* Bc = Bs + cur * B_STG;
            #pragma unroll
            for (int ks = 0; ks < 2; ks++) {
                wmma::fragment<wmma::matrix_a, 16, 16, 16, f16, wmma::row_major> af[4];
                wmma::fragment<wmma::matrix_b, 16, 16, 16, f16, wmma::row_major> bfr[4];
                #pragma unroll
                for (int mi = 0; mi < 4; mi++)
                    wmma::load_matrix_sync(af[mi], Ac + (wm*64 + mi*16)*AS_LD + ks*16, AS_LD);
                #pragma unroll
                for (int ni = 0; ni < 4; ni++)
                    wmma::load_matrix_sync(bfr[ni], Bc + (ks*16)*BS_LD + wn*64 + ni*16, BS_LD);
                #pragma unroll
                for (int mi = 0; mi < 4; mi++)
                    #pragma unroll
                    for (int ni = 0; ni < 4; ni++)
                        wmma::mma_sync(acc[mi][ni], af[mi], bfr[ni], acc[mi][ni]);
            }
            cur = (cur == 2) ? 0 : cur + 1;
            pf  = (pf  == 2) ? 0 : pf  + 1;
        }
        __syncthreads();
    }
};

// fused QKV projection: grid (24, 32); blockIdx.x selects tensor + n-block
__global__ __launch_bounds__(128, 2)
void gemm_qkv(float qscale) {
    extern __shared__ char dynsm[];
    const int tid = threadIdx.x;
    const int wid = tid >> 5, lane = tid & 31;
    const int wm  = wid & 1, wn = wid >> 1;
    const int t   = blockIdx.x >> 3;           // 0=q, 1=k, 2=v
    const int n0  = (blockIdx.x & 7) * 128;
    const int m0  = blockIdx.y * 128;
    const f16* B = (t == 0) ? g_wqh : (t == 1) ? g_wkh : g_wvh;
    f16*       C = (t == 0) ? g_qh  : (t == 1) ? g_kh  : g_vh;
    const float scale = (t == 0) ? qscale : 1.0f;

    GemmCore core;
    core.run(g_xh, B, m0, n0, dynsm, tid);

    float* stgw = ((float*)dynsm) + wid * (16*STG_LD);
    const int srow = lane >> 1, scol = (lane & 1) * 8;
    #pragma unroll
    for (int mi = 0; mi < 4; mi++) {
        #pragma unroll
        for (int ni = 0; ni < 4; ni++) {
            #pragma unroll
            for (int tt = 0; tt < core.acc[mi][ni].num_elements; tt++)
                core.acc[mi][ni].x[tt] *= scale;
            wmma::store_matrix_sync(stgw, core.acc[mi][ni], STG_LD, wmma::mem_row_major);
            __syncwarp();
            const float* sp = stgw + srow*STG_LD + scol;
            union { f16 h[8]; uint4 u; } tmp;
            #pragma unroll
            for (int j = 0; j < 8; j += 2) {
                __half2 p = __floats2half2_rn(sp[j], sp[j+1]);
                tmp.h[j] = p.x;  tmp.h[j+1] = p.y;
            }
            f16* cp = C + (size_t)(m0 + wm*64 + mi*16 + srow) * Eq
                        + n0 + wn*64 + ni*16 + scol;
            *(uint4*)cp = tmp.u;
            __syncwarp();
        }
    }
}

// wo projection: fp32 out
__global__ __launch_bounds__(128, 2)
void gemm_wo() {
    extern __shared__ char dynsm[];
    const int tid = threadIdx.x;
    const int wid = tid >> 5;
    const int wm  = wid & 1, wn = wid >> 1;
    const int m0  = blockIdx.y * 128, n0 = blockIdx.x * 128;

    GemmCore core;
    core.run(g_mixed, g_woh, m0, n0, dynsm, tid);

    #pragma unroll
    for (int mi = 0; mi < 4; mi++)
        #pragma unroll
        for (int ni = 0; ni < 4; ni++)
            wmma::store_matrix_sync(g_attnout + (size_t)(m0 + wm*64 + mi*16) * Eq
                                    + n0 + wn*64 + ni*16,
                                    core.acc[mi][ni], Eq, wmma::mem_row_major);
}

// ---------------- fused flash attention (f16, Q-tile 256, key-tile 64) --------
// 256 threads (8 warps), 32 q-rows per warp (2 m-frags) -> every K/V fragment
// ldsm feeds TWO mmas. Q frags in registers. Half-accum QK^T -> h2exp2 ->
// P f16 (warp-private). Row sums via ones-column in V. 3-stage K/V pipeline,
// one syncthreads per key tile.
#define QS_LD 72
#define KS_LD 72
#define VS_LD 88
#define PS_LD 72
#define OST_LD 84
#define KSTG (64*KS_LD)
#define VSTG (64*VS_LD)
#define OFF_QS 0
#define OFF_KS (256*QS_LD*2)                    // 36864
#define OFF_VS (OFF_KS + 3*KSTG*2)              // +27648 = 64512
#define OFF_PS (OFF_VS + 3*VSTG*2)              // +33792 = 98304
#define SMEM_FLASH (OFF_PS + 256*PS_LD*2)       // +36864 = 135168

__global__ __launch_bounds__(256)
void flash_f16() {
    extern __shared__ char dynsm[];
    f16*   Qs  = (f16*)(dynsm + OFF_QS);
    f16*   Ks  = (f16*)(dynsm + OFF_KS);
    f16*   Vs  = (f16*)(dynsm + OFF_VS);
    f16*   Ps  = (f16*)(dynsm + OFF_PS);
    float* Ost = (float*)dynsm;                  // overlays Qs/Ks/Vs after loop

    const int tid = threadIdx.x;
    const int wid = tid >> 5;
    const int bh  = blockIdx.y, b = bh >> 4, h = bh & 15;
    const int q0  = blockIdx.x * 256;

    const f16* qg  = g_qh + (size_t)(b*Sq + q0) * Eq + h*DKq;
    const f16* kgb = g_kh + (size_t)b * Sq * Eq + h*DKq;
    const f16* vgb = g_vh + (size_t)b * Sq * Eq + h*DKq;

    // load Q: 256 rows x 64 halves = 2048 x16B chunks
    #pragma unroll
    for (int it = 0; it < 8; it++) {
        int c = tid + it*256;
        int r = c >> 3, c8 = (c & 7) * 8;
        *(uint4*)&Qs[r*QS_LD + c8] = *(const uint4*)(qg + (size_t)r * Eq + c8);
    }
    // ones-block of V (cols 64..79, all 3 stages): col 64 = 1, else 0
    for (int idx = tid; idx < 3*1024; idx += 256) {
        int st  = idx >> 10;
        int rem = idx & 1023;
        int r   = rem >> 4, c = 64 + (rem & 15);
        Vs[st*VSTG + r*VS_LD + c] = (c == 64) ? __float2half(1.0f) : __float2half(0.0f);
    }

    const uint32_t ksb = (uint32_t)__cvta_generic_to_shared(Ks);
    const uint32_t vsb = (uint32_t)__cvta_generic_to_shared(Vs);
    int kr[2], kc[2];
    #pragma unroll
    for (int i = 0; i < 2; i++) {
        int c = tid + i*256;
        kr[i] = c >> 3; kc[i] = (c & 7) * 8;
    }

    wmma::fragment<wmma::accumulator, 16, 16, 16, float> Of[2][5];
    #pragma unroll
    for (int mf = 0; mf < 2; mf++)
        #pragma unroll
        for (int nf = 0; nf < 5; nf++) wmma::fill_fragment(Of[mf][nf], 0.0f);

    // preload key tiles 0 and 1 into stages 0,1
    #pragma unroll
    for (int s = 0; s < 2; s++) {
        const size_t go = (size_t)s * 64 * Eq;
        #pragma unroll
        for (int i = 0; i < 2; i++) {
            cpa16(ksb + (uint32_t)(s*KSTG + kr[i]*KS_LD + kc[i])*2,
                  kgb + go + (size_t)kr[i]*Eq + kc[i]);
            cpa16(vsb + (uint32_t)(s*VSTG + kr[i]*VS_LD + kc[i])*2,
                  vgb + go + (size_t)kr[i]*Eq + kc[i]);
        }
        asm volatile("cp.async.commit_group;\n");
    }

    __syncthreads();   // Qs + ones-block visible
    wmma::fragment<wmma::matrix_a, 16, 16, 16, f16, wmma::row_major> qf[2][4];
    #pragma unroll
    for (int mf = 0; mf < 2; mf++)
        #pragma unroll
        for (int kf = 0; kf < 4; kf++)
            wmma::load_matrix_sync(qf[mf][kf], &Qs[(wid*32 + mf*16)*QS_LD + kf*16], QS_LD);

    const int NT = Sq / 64;   // 32
    int cur = 0, pf = 2;
    for (int kt = 0; kt < NT; kt++) {
        if (kt < NT - 1) asm volatile("cp.async.wait_group 1;\n" ::: "memory");
        else             asm volatile("cp.async.wait_group 0;\n" ::: "memory");
        __syncthreads();
        if (kt + 2 < NT) {
            const size_t go = (size_t)(kt + 2) * 64 * Eq;
            #pragma unroll
            for (int i = 0; i < 2; i++) {
                cpa16(ksb + (uint32_t)(pf*KSTG + kr[i]*KS_LD + kc[i])*2,
                      kgb + go + (size_t)kr[i]*Eq + kc[i]);
                cpa16(vsb + (uint32_t)(pf*VSTG + kr[i]*VS_LD + kc[i])*2,
                      vgb + go + (size_t)kr[i]*Eq + kc[i]);
            }
            asm volatile("cp.async.commit_group;\n");
        }
        const f16* Kc = Ks + cur * KSTG;
        const f16* Vc = Vs + cur * VSTG;

        // S = Q @ K^T, half accumulators; each K frag feeds both m-frags
        wmma::fragment<wmma::accumulator, 16, 16, 16, f16> Sacc[2][4];
        #pragma unroll
        for (int mf = 0; mf < 2; mf++)
            #pragma unroll
            for (int nf = 0; nf < 4; nf++)
                wmma::fill_fragment(Sacc[mf][nf], __float2half(0.0f));
        #pragma unroll
        for (int kf = 0; kf < 4; kf++) {
            #pragma unroll
            for (int nf = 0; nf < 4; nf++) {
                wmma::fragment<wmma::matrix_b, 16, 16, 16, f16, wmma::col_major> bfr;
                wmma::load_matrix_sync(bfr, &Kc[(nf*16)*KS_LD + kf*16], KS_LD);
                wmma::mma_sync(Sacc[0][nf], qf[0][kf], bfr, Sacc[0][nf]);
                wmma::mma_sync(Sacc[1][nf], qf[1][kf], bfr, Sacc[1][nf]);
            }
        }
        // P = exp2(S): packed half2 MUFU; store f16 (warp-private)
        #pragma unroll
        for (int mf = 0; mf < 2; mf++)
            #pragma unroll
            for (int nf = 0; nf < 4; nf++) {
                __half2* px = reinterpret_cast<__half2*>(&Sacc[mf][nf].x[0]);
                #pragma unroll
                for (int t = 0; t < 4; t++) px[t] = h2exp2(px[t]);
                wmma::store_matrix_sync(&Ps[(wid*32 + mf*16)*PS_LD + nf*16],
                                        Sacc[mf][nf], PS_LD, wmma::mem_row_major);
            }
        // O += P @ V (5th n-frag = row sums); each V frag feeds both m-frags
        #pragma unroll
        for (int kf = 0; kf < 4; kf++) {
            wmma::fragment<wmma::matrix_a, 16, 16, 16, f16, wmma::row_major> pa[2];
            wmma::load_matrix_sync(pa[0], &Ps[(wid*32)*PS_LD + kf*16], PS_LD);
            wmma::load_matrix_sync(pa[1], &Ps[(wid*32 + 16)*PS_LD + kf*16], PS_LD);
            #pragma unroll
            for (int nf = 0; nf < 5; nf++) {
                wmma::fragment<wmma::matrix_b, 16, 16, 16, f16, wmma::row_major> vb;
                wmma::load_matrix_sync(vb, &Vc[(kf*16)*VS_LD + nf*16], VS_LD);
                wmma::mma_sync(Of[0][nf], pa[0], vb, Of[0][nf]);
                wmma::mma_sync(Of[1][nf], pa[1], vb, Of[1][nf]);
            }
        }
        cur = (cur == 2) ? 0 : cur + 1;
        pf  = (pf  == 2) ? 0 : pf  + 1;
    }

    __syncthreads();
    #pragma unroll
    for (int mf = 0; mf < 2; mf++)
        #pragma unroll
        for (int nf = 0; nf < 5; nf++)
            wmma::store_matrix_sync(&Ost[(wid*32 + mf*16)*OST_LD + nf*16],
                                    Of[mf][nf], OST_LD, wmma::mem_row_major);
    __syncthreads();

    // finalize: one thread per q-row; /l (col 64), +c_attn on d<4
    const float cat = g_cattn;
    const int orow = tid;
    const float inv = 1.0f / Ost[orow*OST_LD + 64];
    f16* og = g_mixed + (size_t)(b*Sq + q0 + orow) * Eq + h*DKq;
    #pragma unroll
    for (int j = 0; j < 16; j++) {
        float4 v = *(float4*)&Ost[orow*OST_LD + j*4];
        v.x *= inv; v.y *= inv; v.z *= inv; v.w *= inv;
        if (j == 0) { v.x += cat; v.y += cat; v.z += cat; v.w += cat; }
        __half2* d = (__half2*)(og + j*4);
        d[0] = __floats2half2_rn(v.x, v.y);
        d[1] = __floats2half2_rn(v.z, v.w);
    }
}

// ---------------- fused LN1+LN2 ----------------
__device__ __forceinline__ float block_reduce_sum(float v) {
    __shared__ float sh[8];
    const int tid = threadIdx.x;
    for (int o = 16; o > 0; o >>= 1) v += __shfl_xor_sync(0xffffffffu, v, o);
    if ((tid & 31) == 0) sh[tid >> 5] = v;
    __syncthreads();
    float r;
    if (tid == 0) {
        r = sh[0];
        for (int i = 1; i < 8; i++) r += sh[i];
        sh[0] = r;
    }
    __syncthreads();
    r = sh[0];
    __syncthreads();
    return r;
}

__global__ __launch_bounds__(256)
void ln12_kernel(const float* __restrict__ x, float* __restrict__ out,
                 const float* __restrict__ g1, const float* __restrict__ b1v,
                 const float* __restrict__ g2, const float* __restrict__ b2v) {
    const size_t row = blockIdx.x;
    const int tid = threadIdx.x;
    float4 xv = *(const float4*)(x + row * Eq + tid*4);
    float4 av = *(const float4*)(g_attnout + row * Eq + tid*4);
    float t[4] = { xv.x+av.x, xv.y+av.y, xv.z+av.z, xv.w+av.w };
    float mean = block_reduce_sum(t[0]+t[1]+t[2]+t[3]) * (1.0f / Eq);
    float vs = 0.f;
    #pragma unroll
    for (int i = 0; i < 4; i++) { float d = t[i] - mean; vs += d*d; }
    float var = block_reduce_sum(vs) * (1.0f / Eq);
    float inv = rsqrtf(var + LN_EPS);
    float4 fv = *(const float4*)(g_ffnvec + tid*4);
    float u[4];
    #pragma unroll
    for (int i = 0; i < 4; i++) {
        int c = tid*4 + i;
        float x1 = (t[i] - mean) * inv * g1[c] + b1v[c];
        u[i] = x1 + ((const float*)&fv)[i];
    }
    float mean2 = block_reduce_sum(u[0]+u[1]+u[2]+u[3]) * (1.0f / Eq);
    float vs2 = 0.f;
    #pragma unroll
    for (int i = 0; i < 4; i++) { float d = u[i] - mean2; vs2 += d*d; }
    float var2 = block_reduce_sum(vs2) * (1.0f / Eq);
    float inv2 = rsqrtf(var2 + LN_EPS);
    float o[4];
    #pragma unroll
    for (int i = 0; i < 4; i++) {
        int c = tid*4 + i;
        o[i] = (u[i] - mean2) * inv2 * g2[c] + b2v[c];
    }
    *(float4*)(out + row * Eq + tid*4) = make_float4(o[0], o[1], o[2], o[3]);
}

// ---------------- launch ----------------
extern "C" void kernel_launch(void* const* d_in, const int* in_sizes, int n_in,
                              void* d_out, int out_size) {
    const float* x    = (const float*)d_in[0];
    const float* wq   = (const float*)d_in[1];
    const float* wk   = (const float*)d_in[2];
    const float* wv   = (const float*)d_in[3];
    const float* wo   = (const float*)d_in[4];
    // d_in[5] = w1, d_in[6] = b1 : mathematically dead (never consumed)
    const float* w2   = (const float*)d_in[7];
    const float* b2   = (const float*)d_in[8];
    const float* qpa  = (const float*)d_in[9];
    const float* qpf  = (const float*)d_in[10];
    const float* ln1g = (const float*)d_in[11];
    const float* ln1b = (const float*)d_in[12];
    const float* ln2g = (const float*)d_in[13];
    const float* ln2b = (const float*)d_in[14];
    float* out = (float*)d_out;

    f16* pxh;
    cudaGetSymbolAddress((void**)&pxh, g_xh);

    cudaFuncSetAttribute(flash_f16,
                         cudaFuncAttributeMaxDynamicSharedMemorySize, SMEM_FLASH);
    cudaFuncSetAttribute(gemm_qkv,
                         cudaFuncAttributeMaxDynamicSharedMemorySize, G_SMEM);
    cudaFuncSetAttribute(gemm_wo,
                         cudaFuncAttributeMaxDynamicSharedMemorySize, G_SMEM);

    prep_kernel<<<1, 1024>>>(qpa, qpf, w2, b2);

    conv_x_kernel<<<(Mq*Eq/4 + 255)/256, 256>>>(x, pxh, Mq*Eq/4);
    conv_w_kernel<<<dim3((Eq*Eq/4 + 255)/256, 4), 256>>>(wq, wk, wv, wo);

    const float qsc = 0.125f * LOG2E;
    gemm_qkv<<<dim3(24, Mq/128), 128, G_SMEM>>>(qsc);

    flash_f16<<<dim3(Sq/256, BHq), 256, SMEM_FLASH>>>();

    gemm_wo<<<dim3(Eq/128, Mq/128), 128, G_SMEM>>>();

    ln12_kernel<<<Mq, 256>>>(x, out, ln1g, ln1b, ln2g, ln2b);
}

// round 13
// speedup vs baseline: 1.2187x; 1.1516x over previous
#include <cuda_runtime.h>
#include <cuda_fp16.h>
#include <mma.h>
#include <math.h>
#include <stdint.h>

using namespace nvcuda;

// Problem dims
#define Bq   2
#define Sq   2048
#define Eq   1024
#define Hq   16
#define DKq  64
#define Mq   (Bq*Sq)    // 4096
#define BHq  (Bq*Hq)    // 32
#define LN_EPS 1e-5f
#define LOG2E 1.442695040888963f

typedef __half f16;

// ---------------- scratch (device globals; no allocs allowed) ----------------
__device__ f16   g_xh[Mq*Eq];
__device__ f16   g_wqh[Eq*Eq];
__device__ f16   g_wkh[Eq*Eq];
__device__ f16   g_wvh[Eq*Eq];
__device__ f16   g_woh[Eq*Eq];
__device__ f16   g_qh[Mq*Eq];           // q f16, pre-scaled by 0.125*log2e
__device__ f16   g_kh[Mq*Eq];
__device__ f16   g_vh[Mq*Eq];
__device__ f16   g_mixed[Mq*Eq];        // attention result (+c_attn), f16
__device__ float g_attnout[Mq*Eq];      // mixed @ wo, fp32
__device__ float g_ffnvec[Eq];          // data-free FFN output vector
__device__ float g_cattn;

__device__ __forceinline__ void cpa16(uint32_t dst, const void* src) {
    asm volatile("cp.async.cg.shared.global [%0], [%1], 16;\n" :: "r"(dst), "l"(src));
}
__device__ __forceinline__ void ldsm4(uint32_t r[4], uint32_t addr) {
    asm volatile("ldmatrix.sync.aligned.m8n8.x4.shared.b16 {%0,%1,%2,%3}, [%4];"
        : "=r"(r[0]), "=r"(r[1]), "=r"(r[2]), "=r"(r[3]) : "r"(addr));
}
__device__ __forceinline__ void ldsm4t(uint32_t r[4], uint32_t addr) {
    asm volatile("ldmatrix.sync.aligned.m8n8.x4.trans.shared.b16 {%0,%1,%2,%3}, [%4];"
        : "=r"(r[0]), "=r"(r[1]), "=r"(r[2]), "=r"(r[3]) : "r"(addr));
}
__device__ __forceinline__ void mma16816_h(uint32_t& d0, uint32_t& d1,
    uint32_t a0, uint32_t a1, uint32_t a2, uint32_t a3, uint32_t b0, uint32_t b1) {
    asm volatile("mma.sync.aligned.m16n8k16.row.col.f16.f16.f16.f16 "
        "{%0,%1},{%2,%3,%4,%5},{%6,%7},{%0,%1};"
        : "+r"(d0), "+r"(d1)
        : "r"(a0), "r"(a1), "r"(a2), "r"(a3), "r"(b0), "r"(b1));
}
__device__ __forceinline__ void mma16816_f(float c[4],
    uint32_t a0, uint32_t a1, uint32_t a2, uint32_t a3, uint32_t b0, uint32_t b1) {
    asm volatile("mma.sync.aligned.m16n8k16.row.col.f32.f16.f16.f32 "
        "{%0,%1,%2,%3},{%4,%5,%6,%7},{%8,%9},{%0,%1,%2,%3};"
        : "+f"(c[0]), "+f"(c[1]), "+f"(c[2]), "+f"(c[3])
        : "r"(a0), "r"(a1), "r"(a2), "r"(a3), "r"(b0), "r"(b1));
}

// ---------------- prep: quantum scalars + collapsed FFN vector ----------------
__global__ void prep_kernel(const float* __restrict__ qp_attn,
                            const float* __restrict__ qp_ffn,
                            const float* __restrict__ w2,
                            const float* __restrict__ b2) {
    int e = threadIdx.x;
    if (e == 0) g_cattn = cosf(qp_attn[0] + qp_attn[1]);
    float cf = cosf(qp_ffn[0] + qp_ffn[1]);
    float rf = cf > 0.f ? cf : 0.f;   // relu
    if (e < Eq) {
        g_ffnvec[e] = rf * (w2[e] + w2[Eq + e] + w2[2*Eq + e] + w2[3*Eq + e]) + b2[e];
    }
}

// ---------------- fp32 -> f16 conversion ------------------------
__global__ __launch_bounds__(256)
void conv_x_kernel(const float* __restrict__ s, f16* __restrict__ d, int n4) {
    int i = blockIdx.x * blockDim.x + threadIdx.x;
    if (i < n4) {
        float4 v = ((const float4*)s)[i];
        ((__half2*)d)[2*i]   = __floats2half2_rn(v.x, v.y);
        ((__half2*)d)[2*i+1] = __floats2half2_rn(v.z, v.w);
    }
}
__global__ __launch_bounds__(256)
void conv_w_kernel(const float* __restrict__ wq, const float* __restrict__ wk,
                   const float* __restrict__ wv, const float* __restrict__ wo) {
    int i = blockIdx.x * blockDim.x + threadIdx.x;
    const int n4 = Eq*Eq/4;
    if (i >= n4) return;
    const float* s; f16* d;
    switch (blockIdx.y) {
        case 0:  s = wq; d = g_wqh; break;
        case 1:  s = wk; d = g_wkh; break;
        case 2:  s = wv; d = g_wvh; break;
        default: s = wo; d = g_woh; break;
    }
    float4 v = ((const float4*)s)[i];
    ((__half2*)d)[2*i]   = __floats2half2_rn(v.x, v.y);
    ((__half2*)d)[2*i+1] = __floats2half2_rn(v.z, v.w);
}

// ---------------- f16 WMMA GEMM core (cp.async 3-stage, BK=32) -----------------
#define AS_LD 40
#define BS_LD 136
#define A_STG (128*AS_LD)
#define B_STG (32*BS_LD)
#define G_OFF_B (3*A_STG*2)
#define G_SMEM  (G_OFF_B + 3*B_STG*2)   // 56832 bytes
#define STG_LD 20

struct GemmCore {
    wmma::fragment<wmma::accumulator, 16, 16, 16, float> acc[4][4];

    __device__ __forceinline__ void run(const f16* A, const f16* B,
                                        int m0, int n0, char* dynsm, int tid) {
        const int wid = tid >> 5;
        const int wm  = wid & 1, wn = wid >> 1;
        f16* As = (f16*)dynsm;
        f16* Bs = (f16*)(dynsm + G_OFF_B);
        const uint32_t asb = (uint32_t)__cvta_generic_to_shared(As);
        const uint32_t bsb = (uint32_t)__cvta_generic_to_shared(Bs);

        const f16* aSrc[4]; uint32_t aDst[4];
        const f16* bSrc[4]; uint32_t bDst[4];
        #pragma unroll
        for (int i = 0; i < 4; i++) {
            int c = tid + i*128;
            int arow = c >> 2, ac8 = (c & 3) * 8;
            aSrc[i] = A + (size_t)(m0 + arow) * Eq + ac8;
            aDst[i] = asb + (uint32_t)(arow*AS_LD + ac8) * 2;
            int brow = c >> 4, bc8 = (c & 15) * 8;
            bSrc[i] = B + (size_t)brow * Eq + n0 + bc8;
            bDst[i] = bsb + (uint32_t)(brow*BS_LD + bc8) * 2;
        }
        #pragma unroll
        for (int mi = 0; mi < 4; mi++)
            #pragma unroll
            for (int ni = 0; ni < 4; ni++)
                wmma::fill_fragment(acc[mi][ni], 0.0f);

        const int niter = Eq / 32;   // 32
        #pragma unroll
        for (int s = 0; s < 2; s++) {
            const uint32_t ao = (uint32_t)(s * A_STG) * 2;
            const uint32_t bo = (uint32_t)(s * B_STG) * 2;
            #pragma unroll
            for (int i = 0; i < 4; i++) cpa16(aDst[i] + ao, aSrc[i] + s*32);
            #pragma unroll
            for (int i = 0; i < 4; i++) cpa16(bDst[i] + bo, bSrc[i] + (size_t)s*32*Eq);
            asm volatile("cp.async.commit_group;\n");
        }

        int cur = 0, pf = 2;
        for (int kb = 0; kb < niter; kb++) {
            if (kb < niter - 1) asm volatile("cp.async.wait_group 1;\n" ::: "memory");
            else                asm volatile("cp.async.wait_group 0;\n" ::: "memory");
            __syncthreads();
            if (kb + 2 < niter) {
                const uint32_t ao = (uint32_t)(pf * A_STG) * 2;
                const uint32_t bo = (uint32_t)(pf * B_STG) * 2;
                const int koffA = (kb + 2) * 32;
                const size_t koffB = (size_t)(kb + 2) * 32 * Eq;
                #pragma unroll
                for (int i = 0; i < 4; i++) cpa16(aDst[i] + ao, aSrc[i] + koffA);
                #pragma unroll
                for (int i = 0; i < 4; i++) cpa16(bDst[i] + bo, bSrc[i] + koffB);
                asm volatile("cp.async.commit_group;\n");
            }
            const f16* Ac = As + cur * A_STG;
            const f16* Bc = Bs + cur * B_STG;
            #pragma unroll
            for (int ks = 0; ks < 2; ks++) {
                wmma::fragment<wmma::matrix_a, 16, 16, 16, f16, wmma::row_major> af[4];
                wmma::fragment<wmma::matrix_b, 16, 16, 16, f16, wmma::row_major> bfr[4];
                #pragma unroll
                for (int mi = 0; mi < 4; mi++)
                    wmma::load_matrix_sync(af[mi], Ac + (wm*64 + mi*16)*AS_LD + ks*16, AS_LD);
                #pragma unroll
                for (int ni = 0; ni < 4; ni++)
                    wmma::load_matrix_sync(bfr[ni], Bc + (ks*16)*BS_LD + wn*64 + ni*16, BS_LD);
                #pragma unroll
                for (int mi = 0; mi < 4; mi++)
                    #pragma unroll
                    for (int ni = 0; ni < 4; ni++)
                        wmma::mma_sync(acc[mi][ni], af[mi], bfr[ni], acc[mi][ni]);
            }
            cur = (cur == 2) ? 0 : cur + 1;
            pf  = (pf  == 2) ? 0 : pf  + 1;
        }
        __syncthreads();
    }
};

// fused QKV projection: grid (24, 32)
__global__ __launch_bounds__(128, 2)
void gemm_qkv(float qscale) {
    extern __shared__ char dynsm[];
    const int tid = threadIdx.x;
    const int wid = tid >> 5, lane = tid & 31;
    const int wm  = wid & 1, wn = wid >> 1;
    const int t   = blockIdx.x >> 3;           // 0=q, 1=k, 2=v
    const int n0  = (blockIdx.x & 7) * 128;
    const int m0  = blockIdx.y * 128;
    const f16* B = (t == 0) ? g_wqh : (t == 1) ? g_wkh : g_wvh;
    f16*       C = (t == 0) ? g_qh  : (t == 1) ? g_kh  : g_vh;
    const float scale = (t == 0) ? qscale : 1.0f;

    GemmCore core;
    core.run(g_xh, B, m0, n0, dynsm, tid);

    float* stgw = ((float*)dynsm) + wid * (16*STG_LD);
    const int srow = lane >> 1, scol = (lane & 1) * 8;
    #pragma unroll
    for (int mi = 0; mi < 4; mi++) {
        #pragma unroll
        for (int ni = 0; ni < 4; ni++) {
            #pragma unroll
            for (int tt = 0; tt < core.acc[mi][ni].num_elements; tt++)
                core.acc[mi][ni].x[tt] *= scale;
            wmma::store_matrix_sync(stgw, core.acc[mi][ni], STG_LD, wmma::mem_row_major);
            __syncwarp();
            const float* sp = stgw + srow*STG_LD + scol;
            union { f16 h[8]; uint4 u; } tmp;
            #pragma unroll
            for (int j = 0; j < 8; j += 2) {
                __half2 p = __floats2half2_rn(sp[j], sp[j+1]);
                tmp.h[j] = p.x;  tmp.h[j+1] = p.y;
            }
            f16* cp = C + (size_t)(m0 + wm*64 + mi*16 + srow) * Eq
                        + n0 + wn*64 + ni*16 + scol;
            *(uint4*)cp = tmp.u;
            __syncwarp();
        }
    }
}

// wo projection: fp32 out
__global__ __launch_bounds__(128, 2)
void gemm_wo() {
    extern __shared__ char dynsm[];
    const int tid = threadIdx.x;
    const int wid = tid >> 5;
    const int wm  = wid & 1, wn = wid >> 1;
    const int m0  = blockIdx.y * 128, n0 = blockIdx.x * 128;

    GemmCore core;
    core.run(g_mixed, g_woh, m0, n0, dynsm, tid);

    #pragma unroll
    for (int mi = 0; mi < 4; mi++)
        #pragma unroll
        for (int ni = 0; ni < 4; ni++)
            wmma::store_matrix_sync(g_attnout + (size_t)(m0 + wm*64 + mi*16) * Eq
                                    + n0 + wn*64 + ni*16,
                                    core.acc[mi][ni], Eq, wmma::mem_row_major);
}

// ---------------- flash attention: raw mma, P in registers --------------------
// 128 threads (4 warps), Q-tile 128 (32 rows/warp = 2 m-frags), key-tile 64.
// S in f16 accumulators -> h2exp2 in regs -> directly A-frags of PV (m16n8k16
// C->A identity). Row sums via constant ones B-frag. 3-stage cp.async K/V.
#define FQ_LD 72
#define FK_LD 72
#define FV_LD 72
#define FKSTG (64*FK_LD)
#define FVSTG (64*FV_LD)
#define FOFF_Q 0
#define FOFF_K (128*FQ_LD*2)                   // 18432
#define FOFF_V (FOFF_K + 3*FKSTG*2)            // +27648 = 46080
#define SMEM_FLASH (FOFF_V + 3*FVSTG*2)        // +27648 = 73728

__global__ __launch_bounds__(128, 2)
void flash_f16() {
    extern __shared__ char dynsm[];
    f16* Qs = (f16*)(dynsm + FOFF_Q);
    const uint32_t qsb = (uint32_t)__cvta_generic_to_shared(dynsm) + FOFF_Q;
    const uint32_t ksb = (uint32_t)__cvta_generic_to_shared(dynsm) + FOFF_K;
    const uint32_t vsb = (uint32_t)__cvta_generic_to_shared(dynsm) + FOFF_V;

    const int tid  = threadIdx.x;
    const int wid  = tid >> 5, lane = tid & 31;
    const int g    = lane >> 2, t4 = lane & 3;
    const int bh   = blockIdx.y, b = bh >> 4, h = bh & 15;
    const int q0   = blockIdx.x * 128;

    const f16* qg  = g_qh + (size_t)(b*Sq + q0) * Eq + h*DKq;
    const f16* kgb = g_kh + (size_t)b * Sq * Eq + h*DKq;
    const f16* vgb = g_vh + (size_t)b * Sq * Eq + h*DKq;

    // stage Q: 128 rows x 64 halves = 1024 16B-chunks, 8/thread
    #pragma unroll
    for (int it = 0; it < 8; it++) {
        int c = tid + it*128;
        int r = c >> 3, c8 = (c & 7) * 8;
        *(uint4*)&Qs[r*FQ_LD + c8] = *(const uint4*)(qg + (size_t)r * Eq + c8);
    }

    // cp.async geometry for K/V tiles (64x64): 512 chunks, 4/thread each
    int cr[4], cc[4];
    #pragma unroll
    for (int i = 0; i < 4; i++) {
        int c = tid + i*128;
        cr[i] = c >> 3; cc[i] = (c & 7) * 8;
    }
    // preload key tiles 0,1 into stages 0,1
    #pragma unroll
    for (int s = 0; s < 2; s++) {
        const size_t go = (size_t)s * 64 * Eq;
        #pragma unroll
        for (int i = 0; i < 4; i++) {
            cpa16(ksb + (uint32_t)(s*FKSTG + cr[i]*FK_LD + cc[i])*2,
                  kgb + go + (size_t)cr[i]*Eq + cc[i]);
            cpa16(vsb + (uint32_t)(s*FVSTG + cr[i]*FV_LD + cc[i])*2,
                  vgb + go + (size_t)cr[i]*Eq + cc[i]);
        }
        asm volatile("cp.async.commit_group;\n");
    }

    __syncthreads();   // Qs visible
    // Q A-frags: 2 m-frags x 4 k-tiles. ldmatrix.x4 lane map:
    //   sel = lane>>3; row += (sel&1)*8; col += (sel>>1)*8  -> regs a0..a3
    uint32_t qa[2][4][4];
    {
        const int qrow = (lane & 7) + ((lane >> 3) & 1) * 8;
        const int qcol = ((lane >> 4) & 1) * 8;
        #pragma unroll
        for (int mi = 0; mi < 2; mi++)
            #pragma unroll
            for (int kk = 0; kk < 4; kk++) {
                uint32_t addr = qsb + (uint32_t)((wid*32 + mi*16 + qrow)*FQ_LD
                                                 + kk*16 + qcol) * 2;
                ldsm4(qa[mi][kk], addr);
            }
    }

    float Of[2][9][4];
    #pragma unroll
    for (int mi = 0; mi < 2; mi++)
        #pragma unroll
        for (int nd = 0; nd < 9; nd++)
            #pragma unroll
            for (int j = 0; j < 4; j++) Of[mi][nd][j] = 0.f;

    // ldmatrix lane offsets:
    // K (non-trans): sel&1 -> d+8, sel>>1 -> key+8
    const int krow = (lane & 7) + ((lane >> 4) & 1) * 8;
    const int kcol = ((lane >> 3) & 1) * 8;
    // V (trans): sel&1 -> k+8, sel>>1 -> n+8
    const int vrow = (lane & 7) + ((lane >> 3) & 1) * 8;
    const int vcol = ((lane >> 4) & 1) * 8;
    // ones B-frag (col 0 of ones tile = 1): n = g -> lanes with g==0
    const uint32_t onesb = (g == 0) ? 0x3C003C00u : 0u;

    const int NT = Sq / 64;   // 32
    int cur = 0, pf = 2;
    for (int kt = 0; kt < NT; kt++) {
        if (kt < NT - 1) asm volatile("cp.async.wait_group 1;\n" ::: "memory");
        else             asm volatile("cp.async.wait_group 0;\n" ::: "memory");
        __syncthreads();
        if (kt + 2 < NT) {
            const size_t go = (size_t)(kt + 2) * 64 * Eq;
            #pragma unroll
            for (int i = 0; i < 4; i++) {
                cpa16(ksb + (uint32_t)(pf*FKSTG + cr[i]*FK_LD + cc[i])*2,
                      kgb + go + (size_t)cr[i]*Eq + cc[i]);
                cpa16(vsb + (uint32_t)(pf*FVSTG + cr[i]*FV_LD + cc[i])*2,
                      vgb + go + (size_t)cr[i]*Eq + cc[i]);
            }
            asm volatile("cp.async.commit_group;\n");
        }
        const uint32_t kbase = ksb + (uint32_t)(cur*FKSTG)*2;
        const uint32_t vbase = vsb + (uint32_t)(cur*FVSTG)*2;

        // S = Q @ K^T  (f16 accum). n-tiles nj=0..7 over 64 keys.
        uint32_t Sc[2][8][2];
        #pragma unroll
        for (int mi = 0; mi < 2; mi++)
            #pragma unroll
            for (int nj = 0; nj < 8; nj++) { Sc[mi][nj][0] = 0u; Sc[mi][nj][1] = 0u; }
        #pragma unroll
        for (int kk = 0; kk < 4; kk++) {
            #pragma unroll
            for (int p = 0; p < 4; p++) {   // key pair-tile: keys p*16..p*16+15
                uint32_t kb[4];
                ldsm4(kb, kbase + (uint32_t)((p*16 + krow)*FK_LD + kk*16 + kcol)*2);
                #pragma unroll
                for (int mi = 0; mi < 2; mi++) {
                    mma16816_h(Sc[mi][2*p][0],   Sc[mi][2*p][1],
                               qa[mi][kk][0], qa[mi][kk][1], qa[mi][kk][2], qa[mi][kk][3],
                               kb[0], kb[1]);
                    mma16816_h(Sc[mi][2*p+1][0], Sc[mi][2*p+1][1],
                               qa[mi][kk][0], qa[mi][kk][1], qa[mi][kk][2], qa[mi][kk][3],
                               kb[2], kb[3]);
                }
            }
        }
        // P = exp2(S) in registers (packed half2)
        #pragma unroll
        for (int mi = 0; mi < 2; mi++)
            #pragma unroll
            for (int nj = 0; nj < 8; nj++) {
                __half2 e0 = h2exp2(*(__half2*)&Sc[mi][nj][0]);
                __half2 e1 = h2exp2(*(__half2*)&Sc[mi][nj][1]);
                Sc[mi][nj][0] = *(uint32_t*)&e0;
                Sc[mi][nj][1] = *(uint32_t*)&e1;
            }
        // O += P @ V.  A-frag of key-k-tile pk = {Sc[2pk].c0, Sc[2pk].c1,
        //   Sc[2pk+1].c0, Sc[2pk+1].c1}  (m16n8k16 C->A identity).
        #pragma unroll
        for (int pk = 0; pk < 4; pk++) {
            #pragma unroll
            for (int ndp = 0; ndp < 4; ndp++) {   // d pair-tiles: d ndp*16..+15
                uint32_t vb[4];
                ldsm4t(vb, vbase + (uint32_t)((pk*16 + vrow)*FV_LD + ndp*16 + vcol)*2);
                #pragma unroll
                for (int mi = 0; mi < 2; mi++) {
                    mma16816_f(Of[mi][2*ndp],
                               Sc[mi][2*pk][0], Sc[mi][2*pk][1],
                               Sc[mi][2*pk+1][0], Sc[mi][2*pk+1][1], vb[0], vb[1]);
                    mma16816_f(Of[mi][2*ndp+1],
                               Sc[mi][2*pk][0], Sc[mi][2*pk][1],
                               Sc[mi][2*pk+1][0], Sc[mi][2*pk+1][1], vb[2], vb[3]);
                }
            }
            #pragma unroll
            for (int mi = 0; mi < 2; mi++)
                mma16816_f(Of[mi][8],
                           Sc[mi][2*pk][0], Sc[mi][2*pk][1],
                           Sc[mi][2*pk+1][0], Sc[mi][2*pk+1][1], onesb, onesb);
        }
        cur = (cur == 2) ? 0 : cur + 1;
        pf  = (pf  == 2) ? 0 : pf  + 1;
    }

    // epilogue: l in Of[mi][8] (col 0 -> t4==0 lanes: c0=row g, c2=row g+8)
    const float cat = g_cattn;
    #pragma unroll
    for (int mi = 0; mi < 2; mi++) {
        float lg  = __shfl_sync(0xffffffffu, Of[mi][8][0], lane & ~3);
        float lg8 = __shfl_sync(0xffffffffu, Of[mi][8][2], lane & ~3);
        float inv0 = 1.0f / lg, inv1 = 1.0f / lg8;
        int r0 = q0 + wid*32 + mi*16 + g;
        f16* og0 = g_mixed + (size_t)(b*Sq + r0) * Eq + h*DKq + 2*t4;
        f16* og1 = og0 + (size_t)8 * Eq;
        const bool addc = (t4 < 2);   // cols 2t4, 2t4+1 < 4 in d-tile 0
        #pragma unroll
        for (int nd = 0; nd < 8; nd++) {
            float a0 = Of[mi][nd][0]*inv0, a1 = Of[mi][nd][1]*inv0;
            float a2 = Of[mi][nd][2]*inv1, a3 = Of[mi][nd][3]*inv1;
            if (nd == 0 && addc) { a0 += cat; a1 += cat; a2 += cat; a3 += cat; }
            __half2 h0 = __floats2half2_rn(a0, a1);
            __half2 h1 = __floats2half2_rn(a2, a3);
            *(__half2*)(og0 + nd*8) = h0;
            *(__half2*)(og1 + nd*8) = h1;
        }
    }
}

// ---------------- fused LN1+LN2 ----------------
__device__ __forceinline__ float block_reduce_sum(float v) {
    __shared__ float sh[8];
    const int tid = threadIdx.x;
    for (int o = 16; o > 0; o >>= 1) v += __shfl_xor_sync(0xffffffffu, v, o);
    if ((tid & 31) == 0) sh[tid >> 5] = v;
    __syncthreads();
    float r;
    if (tid == 0) {
        r = sh[0];
        for (int i = 1; i < 8; i++) r += sh[i];
        sh[0] = r;
    }
    __syncthreads();
    r = sh[0];
    __syncthreads();
    return r;
}

__global__ __launch_bounds__(256)
void ln12_kernel(const float* __restrict__ x, float* __restrict__ out,
                 const float* __restrict__ g1, const float* __restrict__ b1v,
                 const float* __restrict__ g2, const float* __restrict__ b2v) {
    const size_t row = blockIdx.x;
    const int tid = threadIdx.x;
    float4 xv = *(const float4*)(x + row * Eq + tid*4);
    float4 av = *(const float4*)(g_attnout + row * Eq + tid*4);
    float t[4] = { xv.x+av.x, xv.y+av.y, xv.z+av.z, xv.w+av.w };
    float mean = block_reduce_sum(t[0]+t[1]+t[2]+t[3]) * (1.0f / Eq);
    float vs = 0.f;
    #pragma unroll
    for (int i = 0; i < 4; i++) { float d = t[i] - mean; vs += d*d; }
    float var = block_reduce_sum(vs) * (1.0f / Eq);
    float inv = rsqrtf(var + LN_EPS);
    float4 fv = *(const float4*)(g_ffnvec + tid*4);
    float u[4];
    #pragma unroll
    for (int i = 0; i < 4; i++) {
        int c = tid*4 + i;
        float x1 = (t[i] - mean) * inv * g1[c] + b1v[c];
        u[i] = x1 + ((const float*)&fv)[i];
    }
    float mean2 = block_reduce_sum(u[0]+u[1]+u[2]+u[3]) * (1.0f / Eq);
    float vs2 = 0.f;
    #pragma unroll
    for (int i = 0; i < 4; i++) { float d = u[i] - mean2; vs2 += d*d; }
    float var2 = block_reduce_sum(vs2) * (1.0f / Eq);
    float inv2 = rsqrtf(var2 + LN_EPS);
    float o[4];
    #pragma unroll
    for (int i = 0; i < 4; i++) {
        int c = tid*4 + i;
        o[i] = (u[i] - mean2) * inv2 * g2[c] + b2v[c];
    }
    *(float4*)(out + row * Eq + tid*4) = make_float4(o[0], o[1], o[2], o[3]);
}

// ---------------- launch ----------------
extern "C" void kernel_launch(void* const* d_in, const int* in_sizes, int n_in,
                              void* d_out, int out_size) {
    const float* x    = (const float*)d_in[0];
    const float* wq   = (const float*)d_in[1];
    const float* wk   = (const float*)d_in[2];
    const float* wv   = (const float*)d_in[3];
    const float* wo   = (const float*)d_in[4];
    // d_in[5] = w1, d_in[6] = b1 : mathematically dead (never consumed)
    const float* w2   = (const float*)d_in[7];
    const float* b2   = (const float*)d_in[8];
    const float* qpa  = (const float*)d_in[9];
    const float* qpf  = (const float*)d_in[10];
    const float* ln1g = (const float*)d_in[11];
    const float* ln1b = (const float*)d_in[12];
    const float* ln2g = (const float*)d_in[13];
    const float* ln2b = (const float*)d_in[14];
    float* out = (float*)d_out;

    f16* pxh;
    cudaGetSymbolAddress((void**)&pxh, g_xh);

    cudaFuncSetAttribute(flash_f16,
                         cudaFuncAttributeMaxDynamicSharedMemorySize, SMEM_FLASH);
    cudaFuncSetAttribute(gemm_qkv,
                         cudaFuncAttributeMaxDynamicSharedMemorySize, G_SMEM);
    cudaFuncSetAttribute(gemm_wo,
                         cudaFuncAttributeMaxDynamicSharedMemorySize, G_SMEM);

    prep_kernel<<<1, 1024>>>(qpa, qpf, w2, b2);

    conv_x_kernel<<<(Mq*Eq/4 + 255)/256, 256>>>(x, pxh, Mq*Eq/4);
    conv_w_kernel<<<dim3((Eq*Eq/4 + 255)/256, 4), 256>>>(wq, wk, wv, wo);

    const float qsc = 0.125f * LOG2E;
    gemm_qkv<<<dim3(24, Mq/128), 128, G_SMEM>>>(qsc);

    flash_f16<<<dim3(Sq/128, BHq), 128, SMEM_FLASH>>>();

    gemm_wo<<<dim3(Eq/128, Mq/128), 128, G_SMEM>>>();

    ln12_kernel<<<Mq, 256>>>(x, out, ln1g, ln1b, ln2g, ln2b);
}